// round 4
// baseline (speedup 1.0000x reference)
#include <cuda_runtime.h>
#include <cuda_bf16.h>
#include <math.h>
#include <stdint.h>

// ---------------- model dims ----------------
#define BATCH      2
#define SEQ        1024
#define M_ROWS     (BATCH*SEQ)        // 2048
#define D_MODEL    768
#define D_INNER    1536
#define D_STATE    16
#define DT_RANK    48
#define D_CONV     4
#define XDBL_COLS  (DT_RANK + 2*D_STATE)   // 80
#define VOCAB      32000
#define N_LAYER    2
#define EPS        1e-5f

// ---------------- fp32 scratch ----------------
__device__ __align__(16) float g_x    [M_ROWS * D_MODEL];
__device__ __align__(16) float g_xn   [M_ROWS * D_MODEL];
__device__ __align__(16) float g_xr   [M_ROWS * 2 * D_INNER];
__device__ __align__(16) float g_u    [M_ROWS * D_INNER];
__device__ __align__(16) float g_xdbl [M_ROWS * XDBL_COLS];
__device__ __align__(16) float g_delta[M_ROWS * D_INNER];
__device__ __align__(16) float g_y    [M_ROWS * D_INNER];

// ---------------- bf16 hi/lo split buffers ----------------
__device__ __align__(16) __nv_bfloat16 g_emb_h [VOCAB*D_MODEL];
__device__ __align__(16) __nv_bfloat16 g_emb_l [VOCAB*D_MODEL];
__device__ __align__(16) __nv_bfloat16 g_inpw_h[N_LAYER*2*D_INNER*D_MODEL];
__device__ __align__(16) __nv_bfloat16 g_inpw_l[N_LAYER*2*D_INNER*D_MODEL];
__device__ __align__(16) __nv_bfloat16 g_outpw_h[N_LAYER*D_MODEL*D_INNER];
__device__ __align__(16) __nv_bfloat16 g_outpw_l[N_LAYER*D_MODEL*D_INNER];
__device__ __align__(16) __nv_bfloat16 g_xn_h[M_ROWS*D_MODEL];
__device__ __align__(16) __nv_bfloat16 g_xn_l[M_ROWS*D_MODEL];
__device__ __align__(16) __nv_bfloat16 g_u_h [M_ROWS*D_INNER];
__device__ __align__(16) __nv_bfloat16 g_u_l [M_ROWS*D_INNER];
__device__ __align__(16) __nv_bfloat16 g_y_h [M_ROWS*D_INNER];
__device__ __align__(16) __nv_bfloat16 g_y_l [M_ROWS*D_INNER];
__device__ __align__(16) __nv_bfloat16 g_xpw_h[128*D_INNER];
__device__ __align__(16) __nv_bfloat16 g_xpw_l[128*D_INNER];
__device__ __align__(16) __nv_bfloat16 g_dtw_h[D_INNER*64];
__device__ __align__(16) __nv_bfloat16 g_dtw_l[D_INNER*64];
__device__ __align__(16) __nv_bfloat16 g_xdp_h[M_ROWS*64];
__device__ __align__(16) __nv_bfloat16 g_xdp_l[M_ROWS*64];

// ================= small kernels =================
__global__ void embed_kernel(const int* __restrict__ ids,
                             const float* __restrict__ emb,
                             float* __restrict__ x)
{
    int row = blockIdx.x;
    int tok = ids[row];
    const float4* src = (const float4*)(emb + (long)tok * D_MODEL);
    float4* dst = (float4*)(x + (long)row * D_MODEL);
    for (int i = threadIdx.x; i < D_MODEL/4; i += blockDim.x) dst[i] = src[i];
}

__global__ void rmsnorm_kernel(const float* __restrict__ x,
                               const float* __restrict__ w,
                               float* __restrict__ out)
{
    __shared__ float red[8];
    int row = blockIdx.x;
    const float* xp = x + (long)row * D_MODEL;
    float s = 0.f;
    for (int i = threadIdx.x; i < D_MODEL; i += 256) { float v = xp[i]; s += v*v; }
    #pragma unroll
    for (int o = 16; o; o >>= 1) s += __shfl_xor_sync(0xffffffffu, s, o);
    if ((threadIdx.x & 31) == 0) red[threadIdx.x >> 5] = s;
    __syncthreads();
    if (threadIdx.x < 8) {
        float t = red[threadIdx.x];
        #pragma unroll
        for (int o = 4; o; o >>= 1) t += __shfl_xor_sync(0xffu, t, o);
        if (threadIdx.x == 0) red[0] = t;
    }
    __syncthreads();
    float scale = rsqrtf(red[0] / (float)D_MODEL + EPS);
    for (int i = threadIdx.x; i < D_MODEL; i += 256)
        out[(long)row * D_MODEL + i] = xp[i] * scale * w[i];
}

__global__ void split_kernel(const float* __restrict__ s, int n,
                             __nv_bfloat16* __restrict__ h, __nv_bfloat16* __restrict__ l)
{
    int i = blockIdx.x * blockDim.x + threadIdx.x;
    if (i < n) {
        float v = s[i];
        __nv_bfloat16 hb = __float2bfloat16(v);
        h[i] = hb;
        l[i] = __float2bfloat16(v - __bfloat162float(hb));
    }
}

__global__ void split_pad_rows(const float* __restrict__ s, int rows_real, int K,
                               int rows_pad,
                               __nv_bfloat16* __restrict__ h, __nv_bfloat16* __restrict__ l)
{
    int i = blockIdx.x * blockDim.x + threadIdx.x;
    int n = rows_pad * K;
    if (i >= n) return;
    int r = i / K, k = i % K;
    float v = (r < rows_real) ? s[(long)r * K + k] : 0.f;
    __nv_bfloat16 hb = __float2bfloat16(v);
    h[i] = hb;
    l[i] = __float2bfloat16(v - __bfloat162float(hb));
}

__global__ void split_pad_cols(const float* __restrict__ s, int rows, int src_ld,
                               int k_take, int k_pad,
                               __nv_bfloat16* __restrict__ h, __nv_bfloat16* __restrict__ l)
{
    int i = blockIdx.x * blockDim.x + threadIdx.x;
    int n = rows * k_pad;
    if (i >= n) return;
    int r = i / k_pad, k = i % k_pad;
    float v = (k < k_take) ? s[(long)r * src_ld + k] : 0.f;
    __nv_bfloat16 hb = __float2bfloat16(v);
    h[i] = hb;
    l[i] = __float2bfloat16(v - __bfloat162float(hb));
}

__global__ void conv_silu_kernel(const float* __restrict__ xr,
                                 const float* __restrict__ cw,
                                 const float* __restrict__ cb,
                                 float* __restrict__ u)
{
    int idx = blockIdx.x * blockDim.x + threadIdx.x;
    if (idx >= M_ROWS * D_INNER) return;
    int c = idx % D_INNER;
    int m = idx / D_INNER;
    int l = m % SEQ;
    float w0 = cw[c*4+0], w1 = cw[c*4+1], w2 = cw[c*4+2], w3 = cw[c*4+3];
    const float* base = xr + (long)m * (2*D_INNER) + c;
    float acc = cb[c] + w3 * base[0];
    if (l >= 1) acc += w2 * base[-(2*D_INNER)];
    if (l >= 2) acc += w1 * base[-2*(2*D_INNER)];
    if (l >= 3) acc += w0 * base[-3*(2*D_INNER)];
    u[idx] = acc / (1.f + __expf(-acc));
}

__global__ void scan_kernel(const float* __restrict__ delta,
                            const float* __restrict__ u,
                            const float* __restrict__ xdbl,
                            const float* __restrict__ xr,
                            const float* __restrict__ A_log,
                            const float* __restrict__ Dp,
                            float* __restrict__ y)
{
    int gid  = blockIdx.x * (blockDim.x / 16) + (threadIdx.x / 16);
    int lane = threadIdx.x & 15;
    if (gid >= BATCH * D_INNER) return;
    int b  = gid / D_INNER;
    int di = gid % D_INNER;

    float An = -__expf(A_log[di * D_STATE + lane]);
    float Dv = Dp[di];
    float h  = 0.f;

    long m0 = (long)b * SEQ;
    const float* dptr = delta + m0 * D_INNER + di;
    const float* uptr = u     + m0 * D_INNER + di;
    const float* rptr = xr    + m0 * (2*D_INNER) + D_INNER + di;
    const float* bptr = xdbl  + m0 * XDBL_COLS + DT_RANK + lane;
    const float* cptr = xdbl  + m0 * XDBL_COLS + DT_RANK + D_STATE + lane;
    float* yptr       = y     + m0 * D_INNER + di;

    for (int l = 0; l < SEQ; l++) {
        float dv = dptr[(long)l * D_INNER];
        float uv = uptr[(long)l * D_INNER];
        float Bv = bptr[(long)l * XDBL_COLS];
        float Cv = cptr[(long)l * XDBL_COLS];
        float dA = __expf(dv * An);
        h = fmaf(dA, h, dv * Bv * uv);
        float p = h * Cv;
        p += __shfl_xor_sync(0xffffffffu, p, 8);
        p += __shfl_xor_sync(0xffffffffu, p, 4);
        p += __shfl_xor_sync(0xffffffffu, p, 2);
        p += __shfl_xor_sync(0xffffffffu, p, 1);
        if (lane == 0) {
            float rv = rptr[(long)l * (2*D_INNER)];
            float yv = p + uv * Dv;
            yptr[(long)l * D_INNER] = yv * (rv / (1.f + __expf(-rv)));
        }
    }
}

// ================= mma.sync split-bf16 GEMM (templated) =================
// C[M,N] = (Ah+Al)[M,K] @ (Bh+Bl)[N,K]^T, fp32 accum, 3-term split.
// BM x 128 x 32 tiles, BM/64 x 4 warps (warp tile 64x32), NS-stage cp.async.
// A and B fragments both via ldmatrix.x4.
// mode 0: plain   mode 1: softplus(acc + ext[col])   mode 2: acc + ext[row*ldc+col]
// Requires: M%BM==0, K%32==0, B buffers padded to 128-row multiples.
#define GPITCH 40                      // bf16 per smem row (80B): conflict-free ldmatrix

__device__ __forceinline__ uint32_t smem_u32(const void* p) {
    uint32_t a;
    asm("{ .reg .u64 t; cvta.to.shared.u64 t, %1; cvt.u32.u64 %0, t; }" : "=r"(a) : "l"(p));
    return a;
}

#define LDSM_X4(r, addr) \
    asm volatile("ldmatrix.sync.aligned.m8n8.x4.shared.b16 {%0,%1,%2,%3}, [%4];" \
        : "=r"((r)[0]),"=r"((r)[1]),"=r"((r)[2]),"=r"((r)[3]) : "r"(addr))

#define MMA_BF16(c, a, b) \
    asm volatile("mma.sync.aligned.m16n8k16.row.col.f32.bf16.bf16.f32 " \
        "{%0,%1,%2,%3},{%4,%5,%6,%7},{%8,%9},{%0,%1,%2,%3};" \
        : "+f"((c)[0]),"+f"((c)[1]),"+f"((c)[2]),"+f"((c)[3]) \
        : "r"((a)[0]),"r"((a)[1]),"r"((a)[2]),"r"((a)[3]),"r"((b)[0]),"r"((b)[1]))

#define CP16(dst, src) \
    asm volatile("cp.async.cg.shared.global [%0], [%1], 16;" :: "r"(dst), "l"(src))
#define CP_COMMIT() asm volatile("cp.async.commit_group;" ::: "memory")
#define CP_WAIT(n)  asm volatile("cp.async.wait_group %0;" :: "n"(n) : "memory")

template<int BM, int NS>
__global__ void __launch_bounds__(BM*2, (BM==128)?2:1) mma_gemm(
    const __nv_bfloat16* __restrict__ Ah, const __nv_bfloat16* __restrict__ Al,
    const __nv_bfloat16* __restrict__ Bh, const __nv_bfloat16* __restrict__ Bl,
    int K, float* __restrict__ C, int ldc, int Nreal,
    const float* __restrict__ ext, int mode)
{
    constexpr int NTHR        = BM * 2;
    constexpr int STAGE_ELEMS = (2*BM + 256) * GPITCH;
    constexpr int CHUNKS16    = (2*BM + 256) * 4;     // 16B chunks per stage
    constexpr int LITER       = CHUNKS16 / NTHR;

    extern __shared__ __nv_bfloat16 sm[];
    const uint32_t sbase = smem_u32(sm);
    const int tid  = threadIdx.x;
    const int lane = tid & 31;
    const int w    = tid >> 5;
    const int wm   = (w >> 2) << 6;
    const int wn   = (w & 3) << 5;
    const long bm  = (long)blockIdx.y * BM;
    const long bn  = (long)blockIdx.x * 128;

    float acc[4][4][4];
    #pragma unroll
    for (int i = 0; i < 4; i++)
        #pragma unroll
        for (int j = 0; j < 4; j++)
            #pragma unroll
            for (int e = 0; e < 4; e++) acc[i][j][e] = 0.f;

    const int NC = K >> 5;

    // ---- stage loader ----
    #define LOAD_STAGE(st, kc) do {                                           \
        int _k0 = (kc) << 5;                                                  \
        _Pragma("unroll")                                                     \
        for (int _it = 0; _it < LITER; _it++) {                               \
            int _i = _it * NTHR + tid;                                        \
            int _rg = _i >> 2, _ch = _i & 3;                                  \
            const __nv_bfloat16* _gb; long _grow; int _soff;                  \
            if (_rg < 2*BM) {                                                 \
                int _a = _rg >= BM;                                           \
                int _r = _rg - _a * BM;                                       \
                _gb = _a ? Al : Ah; _grow = bm + _r;                          \
                _soff = _rg * GPITCH;                                         \
            } else {                                                          \
                int _rb = _rg - 2*BM;                                         \
                int _a = _rb >= 128;                                          \
                int _r = _rb - _a * 128;                                      \
                _gb = _a ? Bl : Bh; _grow = bn + _r;                          \
                _soff = _rg * GPITCH;                                         \
            }                                                                 \
            const void* _src = _gb + _grow * (long)K + _k0 + _ch * 8;         \
            uint32_t _dst = sbase + ((st) * STAGE_ELEMS + _soff + _ch * 8)*2; \
            CP16(_dst, _src);                                                 \
        }                                                                     \
        CP_COMMIT();                                                          \
    } while (0)

    #pragma unroll
    for (int p = 0; p < NS; p++)
        if (p < NC) LOAD_STAGE(p, p);

    for (int c = 0; c < NC; c++) {
        {
            int rem = NC - 1 - c;                 // loads that may stay pending
            if (NS == 3) {
                if (rem >= 2)      CP_WAIT(2);
                else if (rem == 1) CP_WAIT(1);
                else               CP_WAIT(0);
            } else {
                if (rem >= 1)      CP_WAIT(1);
                else               CP_WAIT(0);
            }
        }
        __syncthreads();

        const int s = c % NS;
        const uint32_t stg = sbase + (s * STAGE_ELEMS) * 2;
        const uint32_t aH = stg;
        const uint32_t aL = stg + (BM * GPITCH) * 2;
        const uint32_t bH = stg + (2 * BM * GPITCH) * 2;
        const uint32_t bL = bH + (128 * GPITCH) * 2;

        #pragma unroll
        for (int ks = 0; ks < 2; ks++) {
            const int k0 = ks << 4;
            // A fragments (hi), B fragments (hi)
            const uint32_t aoff = ((wm + (lane & 15)) * GPITCH
                                   + k0 + ((lane >> 4) << 3)) * 2;
            const int brow = wn + (lane & 7) + ((lane >> 4) << 3);
            const uint32_t boff = (brow * GPITCH + k0 + (((lane >> 3) & 1) << 3)) * 2;

            uint32_t ah[4][4], al[4][4];
            uint32_t bhf[2][4], blf[2][4];   // [pair][4 regs] = ni {0,1} / {2,3}
            #pragma unroll
            for (int mi = 0; mi < 4; mi++)
                LDSM_X4(ah[mi], aH + aoff + mi * 16 * GPITCH * 2);
            LDSM_X4(bhf[0], bH + boff);
            LDSM_X4(bhf[1], bH + boff + 16 * GPITCH * 2);
            #pragma unroll
            for (int mi = 0; mi < 4; mi++)
                #pragma unroll
                for (int ni = 0; ni < 4; ni++)
                    MMA_BF16(acc[mi][ni], ah[mi], &bhf[ni>>1][(ni&1)<<1]);

            LDSM_X4(blf[0], bL + boff);
            LDSM_X4(blf[1], bL + boff + 16 * GPITCH * 2);
            #pragma unroll
            for (int mi = 0; mi < 4; mi++)
                #pragma unroll
                for (int ni = 0; ni < 4; ni++)
                    MMA_BF16(acc[mi][ni], ah[mi], &blf[ni>>1][(ni&1)<<1]);

            #pragma unroll
            for (int mi = 0; mi < 4; mi++)
                LDSM_X4(al[mi], aL + aoff + mi * 16 * GPITCH * 2);
            #pragma unroll
            for (int mi = 0; mi < 4; mi++)
                #pragma unroll
                for (int ni = 0; ni < 4; ni++)
                    MMA_BF16(acc[mi][ni], al[mi], &bhf[ni>>1][(ni&1)<<1]);
        }
        __syncthreads();
        {
            int nx = c + NS;
            if (nx < NC) LOAD_STAGE(s, nx);
        }
    }
    #undef LOAD_STAGE

    // ---- epilogue ----
    const int g  = lane >> 2;
    const int cc = (lane & 3) << 1;
    #pragma unroll
    for (int mi = 0; mi < 4; mi++) {
        #pragma unroll
        for (int ni = 0; ni < 4; ni++) {
            int col = (int)bn + wn + ni * 8 + cc;
            if (col >= Nreal) continue;
            long row0 = bm + wm + mi * 16 + g;
            float v0 = acc[mi][ni][0], v1 = acc[mi][ni][1];
            float v2 = acc[mi][ni][2], v3 = acc[mi][ni][3];
            if (mode == 1) {
                float b0 = ext[col], b1 = ext[col + 1];
                v0 += b0; v1 += b1; v2 += b0; v3 += b1;
                v0 = (v0 > 20.f) ? v0 : log1pf(__expf(v0));
                v1 = (v1 > 20.f) ? v1 : log1pf(__expf(v1));
                v2 = (v2 > 20.f) ? v2 : log1pf(__expf(v2));
                v3 = (v3 > 20.f) ? v3 : log1pf(__expf(v3));
            } else if (mode == 2) {
                v0 += ext[row0 * ldc + col];
                v1 += ext[row0 * ldc + col + 1];
                v2 += ext[(row0 + 8) * ldc + col];
                v3 += ext[(row0 + 8) * ldc + col + 1];
            }
            *(float2*)(C + row0 * ldc + col)       = make_float2(v0, v1);
            *(float2*)(C + (row0 + 8) * ldc + col) = make_float2(v2, v3);
        }
    }
}

#define SMEM_L(BM, NS) ((2*(BM) + 256) * GPITCH * 2 * (NS))

// ================= launch =================
extern "C" void kernel_launch(void* const* d_in, const int* in_sizes, int n_in,
                              void* d_out, int out_size)
{
    const int*   ids    = (const int*)  d_in[0];
    const float* emb    = (const float*)d_in[1];
    const float* normw  = (const float*)d_in[2];
    const float* inpw   = (const float*)d_in[3];
    const float* convw  = (const float*)d_in[4];
    const float* convb  = (const float*)d_in[5];
    const float* xprojw = (const float*)d_in[6];
    const float* dtpw   = (const float*)d_in[7];
    const float* dtpb   = (const float*)d_in[8];
    const float* Alog   = (const float*)d_in[9];
    const float* Dw     = (const float*)d_in[10];
    const float* outpw  = (const float*)d_in[11];
    const float* normf  = (const float*)d_in[12];
    float* out = (float*)d_out;

    float *x, *xn, *xr, *u, *xdbl, *delta, *y;
    cudaGetSymbolAddress((void**)&x,     g_x);
    cudaGetSymbolAddress((void**)&xn,    g_xn);
    cudaGetSymbolAddress((void**)&xr,    g_xr);
    cudaGetSymbolAddress((void**)&u,     g_u);
    cudaGetSymbolAddress((void**)&xdbl,  g_xdbl);
    cudaGetSymbolAddress((void**)&delta, g_delta);
    cudaGetSymbolAddress((void**)&y,     g_y);

    __nv_bfloat16 *emb_h, *emb_l, *inpw_h, *inpw_l, *outpw_h, *outpw_l;
    __nv_bfloat16 *xn_h, *xn_l, *u_h, *u_l, *y_h, *y_l;
    __nv_bfloat16 *xpw_h, *xpw_l, *dtw_h, *dtw_l, *xdp_h, *xdp_l;
    cudaGetSymbolAddress((void**)&emb_h,  g_emb_h);   cudaGetSymbolAddress((void**)&emb_l,  g_emb_l);
    cudaGetSymbolAddress((void**)&inpw_h, g_inpw_h);  cudaGetSymbolAddress((void**)&inpw_l, g_inpw_l);
    cudaGetSymbolAddress((void**)&outpw_h,g_outpw_h); cudaGetSymbolAddress((void**)&outpw_l,g_outpw_l);
    cudaGetSymbolAddress((void**)&xn_h,   g_xn_h);    cudaGetSymbolAddress((void**)&xn_l,   g_xn_l);
    cudaGetSymbolAddress((void**)&u_h,    g_u_h);     cudaGetSymbolAddress((void**)&u_l,    g_u_l);
    cudaGetSymbolAddress((void**)&y_h,    g_y_h);     cudaGetSymbolAddress((void**)&y_l,    g_y_l);
    cudaGetSymbolAddress((void**)&xpw_h,  g_xpw_h);   cudaGetSymbolAddress((void**)&xpw_l,  g_xpw_l);
    cudaGetSymbolAddress((void**)&dtw_h,  g_dtw_h);   cudaGetSymbolAddress((void**)&dtw_l,  g_dtw_l);
    cudaGetSymbolAddress((void**)&xdp_h,  g_xdp_h);   cudaGetSymbolAddress((void**)&xdp_l,  g_xdp_l);

    cudaFuncSetAttribute(mma_gemm<256,3>, cudaFuncAttributeMaxDynamicSharedMemorySize,
                         SMEM_L(256,3));
    cudaFuncSetAttribute(mma_gemm<128,2>, cudaFuncAttributeMaxDynamicSharedMemorySize,
                         SMEM_L(128,2));

    #define SPLIT(src, n, h, l) \
        split_kernel<<<((n) + 511) / 512, 512>>>(src, n, h, l)

    SPLIT(emb,   VOCAB * D_MODEL,                 emb_h,   emb_l);
    SPLIT(inpw,  N_LAYER * 2 * D_INNER * D_MODEL, inpw_h,  inpw_l);
    SPLIT(outpw, N_LAYER * D_MODEL * D_INNER,     outpw_h, outpw_l);

    embed_kernel<<<M_ROWS, 256>>>(ids, emb, x);

    for (int lyr = 0; lyr < N_LAYER; lyr++) {
        rmsnorm_kernel<<<M_ROWS, 256>>>(x, normw + lyr * D_MODEL, xn);
        SPLIT(xn, M_ROWS * D_MODEL, xn_h, xn_l);

        // in_proj: (2048,768) @ (3072,768)^T -> xr     [BM=256]
        mma_gemm<256,3><<<dim3(2*D_INNER/128, M_ROWS/256), 512, SMEM_L(256,3)>>>(
            xn_h, xn_l,
            inpw_h + (long)lyr * 2*D_INNER*D_MODEL,
            inpw_l + (long)lyr * 2*D_INNER*D_MODEL,
            D_MODEL, xr, 2*D_INNER, 2*D_INNER, nullptr, 0);

        conv_silu_kernel<<<(M_ROWS*D_INNER + 255)/256, 256>>>(
            xr, convw + lyr * D_INNER*D_CONV, convb + lyr * D_INNER, u);
        SPLIT(u, M_ROWS * D_INNER, u_h, u_l);

        // x_proj: (2048,1536) @ (80,1536)^T (padded to 128 rows)   [BM=128]
        {
            int n = 128 * D_INNER;
            split_pad_rows<<<(n + 511)/512, 512>>>(
                xprojw + (long)lyr * XDBL_COLS * D_INNER, XDBL_COLS, D_INNER, 128,
                xpw_h, xpw_l);
        }
        mma_gemm<128,2><<<dim3(1, M_ROWS/128), 256, SMEM_L(128,2)>>>(
            u_h, u_l, xpw_h, xpw_l,
            D_INNER, xdbl, XDBL_COLS, XDBL_COLS, nullptr, 0);

        // dt_proj (K padded 48->64) + bias + softplus -> delta     [BM=128]
        {
            int n1 = M_ROWS * 64;
            split_pad_cols<<<(n1 + 511)/512, 512>>>(xdbl, M_ROWS, XDBL_COLS,
                                                    DT_RANK, 64, xdp_h, xdp_l);
            int n2 = D_INNER * 64;
            split_pad_cols<<<(n2 + 511)/512, 512>>>(
                dtpw + (long)lyr * D_INNER * DT_RANK, D_INNER, DT_RANK,
                DT_RANK, 64, dtw_h, dtw_l);
        }
        mma_gemm<128,2><<<dim3(D_INNER/128, M_ROWS/128), 256, SMEM_L(128,2)>>>(
            xdp_h, xdp_l, dtw_h, dtw_l,
            64, delta, D_INNER, D_INNER, dtpb + lyr * D_INNER, 1);

        // selective scan
        scan_kernel<<<(BATCH*D_INNER)/16, 256>>>(
            delta, u, xdbl, xr, Alog + (long)lyr * D_INNER*D_STATE,
            Dw + lyr * D_INNER, y);
        SPLIT(y, M_ROWS * D_INNER, y_h, y_l);

        // out_proj + residual -> x     [BM=128]
        mma_gemm<128,2><<<dim3(D_MODEL/128, M_ROWS/128), 256, SMEM_L(128,2)>>>(
            y_h, y_l,
            outpw_h + (long)lyr * D_MODEL*D_INNER,
            outpw_l + (long)lyr * D_MODEL*D_INNER,
            D_INNER, x, D_MODEL, D_MODEL, x, 2);
    }

    rmsnorm_kernel<<<M_ROWS, 256>>>(x, normf, xn);
    SPLIT(xn, M_ROWS * D_MODEL, xn_h, xn_l);

    // logits: (2048,768) @ (32000,768)^T -> out     [BM=256]
    mma_gemm<256,3><<<dim3(VOCAB/128, M_ROWS/256), 512, SMEM_L(256,3)>>>(
        xn_h, xn_l, emb_h, emb_l,
        D_MODEL, out, VOCAB, VOCAB, nullptr, 0);
}

// round 5
// speedup vs baseline: 1.0371x; 1.0371x over previous
#include <cuda_runtime.h>
#include <cuda_bf16.h>
#include <math.h>
#include <stdint.h>

// ---------------- model dims ----------------
#define BATCH      2
#define SEQ        1024
#define M_ROWS     (BATCH*SEQ)        // 2048
#define D_MODEL    768
#define D_INNER    1536
#define D_STATE    16
#define DT_RANK    48
#define D_CONV     4
#define XDBL_COLS  (DT_RANK + 2*D_STATE)   // 80
#define VOCAB      32000
#define N_LAYER    2
#define EPS        1e-5f

// ---------------- fp32 scratch ----------------
__device__ __align__(16) float g_x    [M_ROWS * D_MODEL];
__device__ __align__(16) float g_xr   [M_ROWS * 2 * D_INNER];
__device__ __align__(16) float g_u    [M_ROWS * D_INNER];
__device__ __align__(16) float g_xdbl [M_ROWS * XDBL_COLS];
__device__ __align__(16) float g_delta[M_ROWS * D_INNER];

// ---------------- bf16 hi/lo split buffers ----------------
__device__ __align__(16) __nv_bfloat16 g_emb_h [VOCAB*D_MODEL];
__device__ __align__(16) __nv_bfloat16 g_emb_l [VOCAB*D_MODEL];
__device__ __align__(16) __nv_bfloat16 g_inpw_h[N_LAYER*2*D_INNER*D_MODEL];
__device__ __align__(16) __nv_bfloat16 g_inpw_l[N_LAYER*2*D_INNER*D_MODEL];
__device__ __align__(16) __nv_bfloat16 g_outpw_h[N_LAYER*D_MODEL*D_INNER];
__device__ __align__(16) __nv_bfloat16 g_outpw_l[N_LAYER*D_MODEL*D_INNER];
__device__ __align__(16) __nv_bfloat16 g_xn_h[M_ROWS*D_MODEL];
__device__ __align__(16) __nv_bfloat16 g_xn_l[M_ROWS*D_MODEL];
__device__ __align__(16) __nv_bfloat16 g_u_h [M_ROWS*D_INNER];
__device__ __align__(16) __nv_bfloat16 g_u_l [M_ROWS*D_INNER];
__device__ __align__(16) __nv_bfloat16 g_y_h [M_ROWS*D_INNER];
__device__ __align__(16) __nv_bfloat16 g_y_l [M_ROWS*D_INNER];
__device__ __align__(16) __nv_bfloat16 g_xpw_h[128*D_INNER];
__device__ __align__(16) __nv_bfloat16 g_xpw_l[128*D_INNER];
__device__ __align__(16) __nv_bfloat16 g_dtw_h[D_INNER*64];
__device__ __align__(16) __nv_bfloat16 g_dtw_l[D_INNER*64];
__device__ __align__(16) __nv_bfloat16 g_xdp_h[M_ROWS*64];
__device__ __align__(16) __nv_bfloat16 g_xdp_l[M_ROWS*64];

// ================= helpers =================
__device__ __forceinline__ void split2(float v, __nv_bfloat16& h, __nv_bfloat16& l) {
    h = __float2bfloat16(v);
    l = __float2bfloat16(v - __bfloat162float(h));
}

// ================= small kernels =================
__global__ void embed_kernel(const int* __restrict__ ids,
                             const float* __restrict__ emb,
                             float* __restrict__ x)
{
    int row = blockIdx.x;
    int tok = ids[row];
    const float4* src = (const float4*)(emb + (long)tok * D_MODEL);
    float4* dst = (float4*)(x + (long)row * D_MODEL);
    for (int i = threadIdx.x; i < D_MODEL/4; i += blockDim.x) dst[i] = src[i];
}

// rmsnorm fused with bf16 hi/lo split (fp32 normalized output not needed)
__global__ void rmsnorm_split_kernel(const float* __restrict__ x,
                                     const float* __restrict__ w,
                                     __nv_bfloat16* __restrict__ oh,
                                     __nv_bfloat16* __restrict__ ol)
{
    __shared__ float red[8];
    int row = blockIdx.x;
    const float* xp = x + (long)row * D_MODEL;
    float s = 0.f;
    for (int i = threadIdx.x; i < D_MODEL; i += 256) { float v = xp[i]; s += v*v; }
    #pragma unroll
    for (int o = 16; o; o >>= 1) s += __shfl_xor_sync(0xffffffffu, s, o);
    if ((threadIdx.x & 31) == 0) red[threadIdx.x >> 5] = s;
    __syncthreads();
    if (threadIdx.x < 8) {
        float t = red[threadIdx.x];
        #pragma unroll
        for (int o = 4; o; o >>= 1) t += __shfl_xor_sync(0xffu, t, o);
        if (threadIdx.x == 0) red[0] = t;
    }
    __syncthreads();
    float scale = rsqrtf(red[0] / (float)D_MODEL + EPS);
    for (int i = threadIdx.x; i < D_MODEL; i += 256) {
        float v = xp[i] * scale * w[i];
        __nv_bfloat16 h, l; split2(v, h, l);
        oh[(long)row * D_MODEL + i] = h;
        ol[(long)row * D_MODEL + i] = l;
    }
}

__global__ void split_kernel(const float* __restrict__ s, int n,
                             __nv_bfloat16* __restrict__ h, __nv_bfloat16* __restrict__ l)
{
    int i = blockIdx.x * blockDim.x + threadIdx.x;
    if (i < n) { __nv_bfloat16 hb, lb; split2(s[i], hb, lb); h[i] = hb; l[i] = lb; }
}

__global__ void split_pad_rows(const float* __restrict__ s, int rows_real, int K,
                               int rows_pad,
                               __nv_bfloat16* __restrict__ h, __nv_bfloat16* __restrict__ l)
{
    int i = blockIdx.x * blockDim.x + threadIdx.x;
    int n = rows_pad * K;
    if (i >= n) return;
    int r = i / K, k = i % K;
    float v = (r < rows_real) ? s[(long)r * K + k] : 0.f;
    __nv_bfloat16 hb, lb; split2(v, hb, lb);
    h[i] = hb; l[i] = lb;
}

__global__ void split_pad_cols(const float* __restrict__ s, int rows, int src_ld,
                               int k_take, int k_pad,
                               __nv_bfloat16* __restrict__ h, __nv_bfloat16* __restrict__ l)
{
    int i = blockIdx.x * blockDim.x + threadIdx.x;
    int n = rows * k_pad;
    if (i >= n) return;
    int r = i / k_pad, k = i % k_pad;
    float v = (k < k_take) ? s[(long)r * src_ld + k] : 0.f;
    __nv_bfloat16 hb, lb; split2(v, hb, lb);
    h[i] = hb; l[i] = lb;
}

// causal depthwise conv(4) + bias + silu, fused with bf16 split of u
__global__ void conv_silu_split_kernel(const float* __restrict__ xr,
                                       const float* __restrict__ cw,
                                       const float* __restrict__ cb,
                                       float* __restrict__ u,
                                       __nv_bfloat16* __restrict__ uh,
                                       __nv_bfloat16* __restrict__ ul)
{
    int idx = blockIdx.x * blockDim.x + threadIdx.x;
    if (idx >= M_ROWS * D_INNER) return;
    int c = idx % D_INNER;
    int m = idx / D_INNER;
    int l = m % SEQ;
    float w0 = cw[c*4+0], w1 = cw[c*4+1], w2 = cw[c*4+2], w3 = cw[c*4+3];
    const float* base = xr + (long)m * (2*D_INNER) + c;
    float acc = cb[c] + w3 * base[0];
    if (l >= 1) acc += w2 * base[-(2*D_INNER)];
    if (l >= 2) acc += w1 * base[-2*(2*D_INNER)];
    if (l >= 3) acc += w0 * base[-3*(2*D_INNER)];
    float v = acc / (1.f + __expf(-acc));
    u[idx] = v;
    __nv_bfloat16 hb, lb; split2(v, hb, lb);
    uh[idx] = hb; ul[idx] = lb;
}

// selective scan fused: D skip + silu(res) gate + bf16 split of y
__global__ void scan_kernel(const float* __restrict__ delta,
                            const float* __restrict__ u,
                            const float* __restrict__ xdbl,
                            const float* __restrict__ xr,
                            const float* __restrict__ A_log,
                            const float* __restrict__ Dp,
                            __nv_bfloat16* __restrict__ yh,
                            __nv_bfloat16* __restrict__ yl)
{
    int gid  = blockIdx.x * (blockDim.x / 16) + (threadIdx.x / 16);
    int lane = threadIdx.x & 15;
    if (gid >= BATCH * D_INNER) return;
    int b  = gid / D_INNER;
    int di = gid % D_INNER;

    float An = -__expf(A_log[di * D_STATE + lane]);
    float Dv = Dp[di];
    float h  = 0.f;

    long m0 = (long)b * SEQ;
    const float* dptr = delta + m0 * D_INNER + di;
    const float* uptr = u     + m0 * D_INNER + di;
    const float* rptr = xr    + m0 * (2*D_INNER) + D_INNER + di;
    const float* bptr = xdbl  + m0 * XDBL_COLS + DT_RANK + lane;
    const float* cptr = xdbl  + m0 * XDBL_COLS + DT_RANK + D_STATE + lane;

    for (int l = 0; l < SEQ; l++) {
        float dv = dptr[(long)l * D_INNER];
        float uv = uptr[(long)l * D_INNER];
        float Bv = bptr[(long)l * XDBL_COLS];
        float Cv = cptr[(long)l * XDBL_COLS];
        float dA = __expf(dv * An);
        h = fmaf(dA, h, dv * Bv * uv);
        float p = h * Cv;
        p += __shfl_xor_sync(0xffffffffu, p, 8);
        p += __shfl_xor_sync(0xffffffffu, p, 4);
        p += __shfl_xor_sync(0xffffffffu, p, 2);
        p += __shfl_xor_sync(0xffffffffu, p, 1);
        if (lane == 0) {
            float rv = rptr[(long)l * (2*D_INNER)];
            float yv = (p + uv * Dv) * (rv / (1.f + __expf(-rv)));
            __nv_bfloat16 hb, lb; split2(yv, hb, lb);
            yh[m0 * D_INNER + (long)l * D_INNER + di] = hb;
            yl[m0 * D_INNER + (long)l * D_INNER + di] = lb;
        }
    }
}

// ================= mma.sync split-bf16 GEMM =================
// C[M,N] = (Ah+Al)[M,K] @ (Bh+Bl)[N,K]^T, fp32 accum, 3-term split.
// 128x128x32 tiles, 8 warps (2Mx4N), 2-stage cp.async, A and B via ldmatrix.x4.
// mode 0: plain
// mode 1: softplus(acc + ext[col])
// mode 2: acc + ext[row*ldc+col]
// mode 3: plain C, plus bf16 split-pad write to xdph/xdpl (stride 64, cols<48 data)
#define GPITCH 40

__device__ __forceinline__ uint32_t smem_u32(const void* p) {
    uint32_t a;
    asm("{ .reg .u64 t; cvta.to.shared.u64 t, %1; cvt.u32.u64 %0, t; }" : "=r"(a) : "l"(p));
    return a;
}

#define LDSM_X4(r, addr) \
    asm volatile("ldmatrix.sync.aligned.m8n8.x4.shared.b16 {%0,%1,%2,%3}, [%4];" \
        : "=r"((r)[0]),"=r"((r)[1]),"=r"((r)[2]),"=r"((r)[3]) : "r"(addr))

#define MMA_BF16(c, a, b) \
    asm volatile("mma.sync.aligned.m16n8k16.row.col.f32.bf16.bf16.f32 " \
        "{%0,%1,%2,%3},{%4,%5,%6,%7},{%8,%9},{%0,%1,%2,%3};" \
        : "+f"((c)[0]),"+f"((c)[1]),"+f"((c)[2]),"+f"((c)[3]) \
        : "r"((a)[0]),"r"((a)[1]),"r"((a)[2]),"r"((a)[3]),"r"((b)[0]),"r"((b)[1]))

#define CP16(dst, src) \
    asm volatile("cp.async.cg.shared.global [%0], [%1], 16;" :: "r"(dst), "l"(src))
#define CP_COMMIT() asm volatile("cp.async.commit_group;" ::: "memory")
#define CP_WAIT(n)  asm volatile("cp.async.wait_group %0;" :: "n"(n) : "memory")

#define STAGE_ELEMS (512 * GPITCH)           // (2*128 A + 2*128 B) rows x 40
#define GSMEM_BYTES (2 * STAGE_ELEMS * 2)    // 81920 B

__global__ void __launch_bounds__(256, 2) mma_gemm(
    const __nv_bfloat16* __restrict__ Ah, const __nv_bfloat16* __restrict__ Al,
    const __nv_bfloat16* __restrict__ Bh, const __nv_bfloat16* __restrict__ Bl,
    int K, float* __restrict__ C, int ldc, int Nreal,
    const float* __restrict__ ext, int mode,
    __nv_bfloat16* __restrict__ xdph, __nv_bfloat16* __restrict__ xdpl)
{
    extern __shared__ __nv_bfloat16 sm[];
    const uint32_t sbase = smem_u32(sm);
    const int tid  = threadIdx.x;
    const int lane = tid & 31;
    const int w    = tid >> 5;
    const int wm   = (w >> 2) << 6;
    const int wn   = (w & 3) << 5;
    const long bm  = (long)blockIdx.y * 128;
    const long bn  = (long)blockIdx.x * 128;

    float acc[4][4][4];
    #pragma unroll
    for (int i = 0; i < 4; i++)
        #pragma unroll
        for (int j = 0; j < 4; j++)
            #pragma unroll
            for (int e = 0; e < 4; e++) acc[i][j][e] = 0.f;

    const int NC = K >> 5;

    #define LOAD_STAGE(st, kc) do {                                           \
        int _k0 = (kc) << 5;                                                  \
        _Pragma("unroll")                                                     \
        for (int _it = 0; _it < 8; _it++) {                                   \
            int _i = _it * 256 + tid;                                         \
            int _rg = _i >> 2, _ch = _i & 3;                                  \
            const __nv_bfloat16* _gb; long _grow;                             \
            if (_rg < 256) {                                                  \
                int _a = _rg >= 128;                                          \
                _gb = _a ? Al : Ah; _grow = bm + (_rg - _a * 128);            \
            } else {                                                          \
                int _rb = _rg - 256;                                          \
                int _a = _rb >= 128;                                          \
                _gb = _a ? Bl : Bh; _grow = bn + (_rb - _a * 128);            \
            }                                                                 \
            const void* _src = _gb + _grow * (long)K + _k0 + _ch * 8;         \
            uint32_t _dst = sbase + ((st) * STAGE_ELEMS + _rg * GPITCH        \
                                     + _ch * 8) * 2;                          \
            CP16(_dst, _src);                                                 \
        }                                                                     \
        CP_COMMIT();                                                          \
    } while (0)

    LOAD_STAGE(0, 0);
    LOAD_STAGE(1, 1);

    for (int c = 0; c < NC; c++) {
        if (c + 1 < NC) CP_WAIT(1);
        else            CP_WAIT(0);
        __syncthreads();

        const int s = c & 1;
        const uint32_t stg = sbase + (s * STAGE_ELEMS) * 2;
        const uint32_t aH = stg;
        const uint32_t aL = stg + (128 * GPITCH) * 2;
        const uint32_t bH = stg + (256 * GPITCH) * 2;
        const uint32_t bL = stg + (384 * GPITCH) * 2;

        #pragma unroll
        for (int ks = 0; ks < 2; ks++) {
            const int k0 = ks << 4;
            const uint32_t aoff = ((wm + (lane & 15)) * GPITCH
                                   + k0 + ((lane >> 4) << 3)) * 2;
            const int brow = wn + (lane & 7) + ((lane >> 4) << 3);
            const uint32_t boff = (brow * GPITCH + k0 + (((lane >> 3) & 1) << 3)) * 2;

            uint32_t ah[4][4], al[4][4];
            uint32_t bhf[2][4], blf[2][4];
            #pragma unroll
            for (int mi = 0; mi < 4; mi++)
                LDSM_X4(ah[mi], aH + aoff + mi * 16 * GPITCH * 2);
            LDSM_X4(bhf[0], bH + boff);
            LDSM_X4(bhf[1], bH + boff + 16 * GPITCH * 2);
            #pragma unroll
            for (int mi = 0; mi < 4; mi++)
                #pragma unroll
                for (int ni = 0; ni < 4; ni++)
                    MMA_BF16(acc[mi][ni], ah[mi], &bhf[ni>>1][(ni&1)<<1]);

            LDSM_X4(blf[0], bL + boff);
            LDSM_X4(blf[1], bL + boff + 16 * GPITCH * 2);
            #pragma unroll
            for (int mi = 0; mi < 4; mi++)
                #pragma unroll
                for (int ni = 0; ni < 4; ni++)
                    MMA_BF16(acc[mi][ni], ah[mi], &blf[ni>>1][(ni&1)<<1]);

            #pragma unroll
            for (int mi = 0; mi < 4; mi++)
                LDSM_X4(al[mi], aL + aoff + mi * 16 * GPITCH * 2);
            #pragma unroll
            for (int mi = 0; mi < 4; mi++)
                #pragma unroll
                for (int ni = 0; ni < 4; ni++)
                    MMA_BF16(acc[mi][ni], al[mi], &bhf[ni>>1][(ni&1)<<1]);
        }
        __syncthreads();
        if (c + 2 < NC) LOAD_STAGE(s, c + 2);
    }
    #undef LOAD_STAGE

    // ---- epilogue ----
    const int g  = lane >> 2;
    const int cc = (lane & 3) << 1;
    #pragma unroll
    for (int mi = 0; mi < 4; mi++) {
        #pragma unroll
        for (int ni = 0; ni < 4; ni++) {
            int col = (int)bn + wn + ni * 8 + cc;
            long row0 = bm + wm + mi * 16 + g;
            float v0 = acc[mi][ni][0], v1 = acc[mi][ni][1];
            float v2 = acc[mi][ni][2], v3 = acc[mi][ni][3];
            if (mode == 1) {
                float b0 = ext[col], b1 = ext[col + 1];
                v0 += b0; v1 += b1; v2 += b0; v3 += b1;
                v0 = (v0 > 20.f) ? v0 : log1pf(__expf(v0));
                v1 = (v1 > 20.f) ? v1 : log1pf(__expf(v1));
                v2 = (v2 > 20.f) ? v2 : log1pf(__expf(v2));
                v3 = (v3 > 20.f) ? v3 : log1pf(__expf(v3));
            } else if (mode == 2) {
                v0 += ext[row0 * ldc + col];
                v1 += ext[row0 * ldc + col + 1];
                v2 += ext[(row0 + 8) * ldc + col];
                v3 += ext[(row0 + 8) * ldc + col + 1];
            }
            if (col < Nreal) {
                *(float2*)(C + row0 * ldc + col)       = make_float2(v0, v1);
                *(float2*)(C + (row0 + 8) * ldc + col) = make_float2(v2, v3);
            }
            if (mode == 3 && col < 64) {
                float p0 = (col     < DT_RANK) ? v0 : 0.f;
                float p1 = (col + 1 < DT_RANK) ? v1 : 0.f;
                float p2 = (col     < DT_RANK) ? v2 : 0.f;
                float p3 = (col + 1 < DT_RANK) ? v3 : 0.f;
                __nv_bfloat16 h, l;
                split2(p0, h, l); xdph[row0*64 + col]     = h; xdpl[row0*64 + col]     = l;
                split2(p1, h, l); xdph[row0*64 + col + 1] = h; xdpl[row0*64 + col + 1] = l;
                split2(p2, h, l); xdph[(row0+8)*64 + col]     = h; xdpl[(row0+8)*64 + col]     = l;
                split2(p3, h, l); xdph[(row0+8)*64 + col + 1] = h; xdpl[(row0+8)*64 + col + 1] = l;
            }
        }
    }
}

// ================= launch =================
extern "C" void kernel_launch(void* const* d_in, const int* in_sizes, int n_in,
                              void* d_out, int out_size)
{
    const int*   ids    = (const int*)  d_in[0];
    const float* emb    = (const float*)d_in[1];
    const float* normw  = (const float*)d_in[2];
    const float* inpw   = (const float*)d_in[3];
    const float* convw  = (const float*)d_in[4];
    const float* convb  = (const float*)d_in[5];
    const float* xprojw = (const float*)d_in[6];
    const float* dtpw   = (const float*)d_in[7];
    const float* dtpb   = (const float*)d_in[8];
    const float* Alog   = (const float*)d_in[9];
    const float* Dw     = (const float*)d_in[10];
    const float* outpw  = (const float*)d_in[11];
    const float* normf  = (const float*)d_in[12];
    float* out = (float*)d_out;

    float *x, *xr, *u, *xdbl, *delta;
    cudaGetSymbolAddress((void**)&x,     g_x);
    cudaGetSymbolAddress((void**)&xr,    g_xr);
    cudaGetSymbolAddress((void**)&u,     g_u);
    cudaGetSymbolAddress((void**)&xdbl,  g_xdbl);
    cudaGetSymbolAddress((void**)&delta, g_delta);

    __nv_bfloat16 *emb_h, *emb_l, *inpw_h, *inpw_l, *outpw_h, *outpw_l;
    __nv_bfloat16 *xn_h, *xn_l, *u_h, *u_l, *y_h, *y_l;
    __nv_bfloat16 *xpw_h, *xpw_l, *dtw_h, *dtw_l, *xdp_h, *xdp_l;
    cudaGetSymbolAddress((void**)&emb_h,  g_emb_h);   cudaGetSymbolAddress((void**)&emb_l,  g_emb_l);
    cudaGetSymbolAddress((void**)&inpw_h, g_inpw_h);  cudaGetSymbolAddress((void**)&inpw_l, g_inpw_l);
    cudaGetSymbolAddress((void**)&outpw_h,g_outpw_h); cudaGetSymbolAddress((void**)&outpw_l,g_outpw_l);
    cudaGetSymbolAddress((void**)&xn_h,   g_xn_h);    cudaGetSymbolAddress((void**)&xn_l,   g_xn_l);
    cudaGetSymbolAddress((void**)&u_h,    g_u_h);     cudaGetSymbolAddress((void**)&u_l,    g_u_l);
    cudaGetSymbolAddress((void**)&y_h,    g_y_h);     cudaGetSymbolAddress((void**)&y_l,    g_y_l);
    cudaGetSymbolAddress((void**)&xpw_h,  g_xpw_h);   cudaGetSymbolAddress((void**)&xpw_l,  g_xpw_l);
    cudaGetSymbolAddress((void**)&dtw_h,  g_dtw_h);   cudaGetSymbolAddress((void**)&dtw_l,  g_dtw_l);
    cudaGetSymbolAddress((void**)&xdp_h,  g_xdp_h);   cudaGetSymbolAddress((void**)&xdp_l,  g_xdp_l);

    cudaFuncSetAttribute(mma_gemm, cudaFuncAttributeMaxDynamicSharedMemorySize,
                         GSMEM_BYTES);

    #define SPLIT(src, n, h, l) \
        split_kernel<<<((n) + 511) / 512, 512>>>(src, n, h, l)

    // Launch order chosen so the 4th kernel launch (idx 3) is the in_proj GEMM
    // (the ncu capture window lands there).
    embed_kernel<<<M_ROWS, 256>>>(ids, emb, x);                               // 0
    SPLIT(inpw, N_LAYER * 2 * D_INNER * D_MODEL, inpw_h, inpw_l);             // 1

    for (int lyr = 0; lyr < N_LAYER; lyr++) {
        rmsnorm_split_kernel<<<M_ROWS, 256>>>(x, normw + lyr * D_MODEL,
                                              xn_h, xn_l);                    // 2

        // in_proj: (2048,768) @ (3072,768)^T -> xr                           // 3 (profiled)
        mma_gemm<<<dim3(2*D_INNER/128, M_ROWS/128), 256, GSMEM_BYTES>>>(
            xn_h, xn_l,
            inpw_h + (long)lyr * 2*D_INNER*D_MODEL,
            inpw_l + (long)lyr * 2*D_INNER*D_MODEL,
            D_MODEL, xr, 2*D_INNER, 2*D_INNER, nullptr, 0, nullptr, nullptr);

        conv_silu_split_kernel<<<(M_ROWS*D_INNER + 255)/256, 256>>>(
            xr, convw + lyr * D_INNER*D_CONV, convb + lyr * D_INNER,
            u, u_h, u_l);

        {
            int n = 128 * D_INNER;
            split_pad_rows<<<(n + 511)/512, 512>>>(
                xprojw + (long)lyr * XDBL_COLS * D_INNER, XDBL_COLS, D_INNER, 128,
                xpw_h, xpw_l);
        }
        // x_proj: (2048,1536) @ (80,1536)^T -> xdbl + fused dt-input split/pad
        mma_gemm<<<dim3(1, M_ROWS/128), 256, GSMEM_BYTES>>>(
            u_h, u_l, xpw_h, xpw_l,
            D_INNER, xdbl, XDBL_COLS, XDBL_COLS, nullptr, 3, xdp_h, xdp_l);

        {
            int n2 = D_INNER * 64;
            split_pad_cols<<<(n2 + 511)/512, 512>>>(
                dtpw + (long)lyr * D_INNER * DT_RANK, D_INNER, DT_RANK,
                DT_RANK, 64, dtw_h, dtw_l);
        }
        // dt_proj (K=64) + bias + softplus -> delta
        mma_gemm<<<dim3(D_INNER/128, M_ROWS/128), 256, GSMEM_BYTES>>>(
            xdp_h, xdp_l, dtw_h, dtw_l,
            64, delta, D_INNER, D_INNER, dtpb + lyr * D_INNER, 1,
            nullptr, nullptr);

        // selective scan (writes y split directly)
        scan_kernel<<<(BATCH*D_INNER)/16, 256>>>(
            delta, u, xdbl, xr, Alog + (long)lyr * D_INNER*D_STATE,
            Dw + lyr * D_INNER, y_h, y_l);

        if (lyr == 0)
            SPLIT(outpw, N_LAYER * D_MODEL * D_INNER, outpw_h, outpw_l);

        // out_proj + residual -> x
        mma_gemm<<<dim3(D_MODEL/128, M_ROWS/128), 256, GSMEM_BYTES>>>(
            y_h, y_l,
            outpw_h + (long)lyr * D_MODEL*D_INNER,
            outpw_l + (long)lyr * D_MODEL*D_INNER,
            D_INNER, x, D_MODEL, D_MODEL, x, 2, nullptr, nullptr);
    }

    SPLIT(emb, VOCAB * D_MODEL, emb_h, emb_l);
    rmsnorm_split_kernel<<<M_ROWS, 256>>>(x, normf, xn_h, xn_l);

    // logits: (2048,768) @ (32000,768)^T -> out
    mma_gemm<<<dim3(VOCAB/128, M_ROWS/128), 256, GSMEM_BYTES>>>(
        xn_h, xn_l, emb_h, emb_l,
        D_MODEL, out, VOCAB, VOCAB, nullptr, 0, nullptr, nullptr);
}

// round 6
// speedup vs baseline: 1.0872x; 1.0483x over previous
#include <cuda_runtime.h>
#include <cuda_bf16.h>
#include <math.h>
#include <stdint.h>

// ---------------- model dims ----------------
#define BATCH      2
#define SEQ        1024
#define M_ROWS     (BATCH*SEQ)        // 2048
#define D_MODEL    768
#define D_INNER    1536
#define D_STATE    16
#define DT_RANK    48
#define D_CONV     4
#define XDBL_COLS  (DT_RANK + 2*D_STATE)   // 80
#define VOCAB      32000
#define N_LAYER    2
#define EPS        1e-5f

// ---------------- fp32 scratch ----------------
__device__ __align__(16) float g_x    [M_ROWS * D_MODEL];
__device__ __align__(16) float g_xr   [M_ROWS * 2 * D_INNER];
__device__ __align__(16) float g_u    [M_ROWS * D_INNER];
__device__ __align__(16) float g_xdbl [M_ROWS * XDBL_COLS];
__device__ __align__(16) float g_delta[M_ROWS * D_INNER];
__device__ __align__(16) float g_part [4 * M_ROWS * D_MODEL];  // split-K partials (max use)

// ---------------- bf16 hi/lo split buffers ----------------
__device__ __align__(16) __nv_bfloat16 g_emb_h [VOCAB*D_MODEL];
__device__ __align__(16) __nv_bfloat16 g_emb_l [VOCAB*D_MODEL];
__device__ __align__(16) __nv_bfloat16 g_inpw_h[N_LAYER*2*D_INNER*D_MODEL];
__device__ __align__(16) __nv_bfloat16 g_inpw_l[N_LAYER*2*D_INNER*D_MODEL];
__device__ __align__(16) __nv_bfloat16 g_outpw_h[N_LAYER*D_MODEL*D_INNER];
__device__ __align__(16) __nv_bfloat16 g_outpw_l[N_LAYER*D_MODEL*D_INNER];
__device__ __align__(16) __nv_bfloat16 g_xn_h[M_ROWS*D_MODEL];
__device__ __align__(16) __nv_bfloat16 g_xn_l[M_ROWS*D_MODEL];
__device__ __align__(16) __nv_bfloat16 g_u_h [M_ROWS*D_INNER];
__device__ __align__(16) __nv_bfloat16 g_u_l [M_ROWS*D_INNER];
__device__ __align__(16) __nv_bfloat16 g_y_h [M_ROWS*D_INNER];
__device__ __align__(16) __nv_bfloat16 g_y_l [M_ROWS*D_INNER];
__device__ __align__(16) __nv_bfloat16 g_xpw_h[128*D_INNER];
__device__ __align__(16) __nv_bfloat16 g_xpw_l[128*D_INNER];
__device__ __align__(16) __nv_bfloat16 g_dtw_h[D_INNER*64];
__device__ __align__(16) __nv_bfloat16 g_dtw_l[D_INNER*64];
__device__ __align__(16) __nv_bfloat16 g_xdp_h[M_ROWS*64];
__device__ __align__(16) __nv_bfloat16 g_xdp_l[M_ROWS*64];

// ================= helpers =================
__device__ __forceinline__ void split2(float v, __nv_bfloat16& h, __nv_bfloat16& l) {
    h = __float2bfloat16(v);
    l = __float2bfloat16(v - __bfloat162float(h));
}

// ================= small kernels =================
__global__ void embed_kernel(const int* __restrict__ ids,
                             const float* __restrict__ emb,
                             float* __restrict__ x)
{
    int row = blockIdx.x;
    int tok = ids[row];
    const float4* src = (const float4*)(emb + (long)tok * D_MODEL);
    float4* dst = (float4*)(x + (long)row * D_MODEL);
    for (int i = threadIdx.x; i < D_MODEL/4; i += blockDim.x) dst[i] = src[i];
}

__global__ void rmsnorm_split_kernel(const float* __restrict__ x,
                                     const float* __restrict__ w,
                                     __nv_bfloat16* __restrict__ oh,
                                     __nv_bfloat16* __restrict__ ol)
{
    __shared__ float red[8];
    int row = blockIdx.x;
    const float* xp = x + (long)row * D_MODEL;
    float s = 0.f;
    for (int i = threadIdx.x; i < D_MODEL; i += 256) { float v = xp[i]; s += v*v; }
    #pragma unroll
    for (int o = 16; o; o >>= 1) s += __shfl_xor_sync(0xffffffffu, s, o);
    if ((threadIdx.x & 31) == 0) red[threadIdx.x >> 5] = s;
    __syncthreads();
    if (threadIdx.x < 8) {
        float t = red[threadIdx.x];
        #pragma unroll
        for (int o = 4; o; o >>= 1) t += __shfl_xor_sync(0xffu, t, o);
        if (threadIdx.x == 0) red[0] = t;
    }
    __syncthreads();
    float scale = rsqrtf(red[0] / (float)D_MODEL + EPS);
    for (int i = threadIdx.x; i < D_MODEL; i += 256) {
        float v = xp[i] * scale * w[i];
        __nv_bfloat16 h, l; split2(v, h, l);
        oh[(long)row * D_MODEL + i] = h;
        ol[(long)row * D_MODEL + i] = l;
    }
}

// vectorized fp32 -> bf16 hi/lo split (4 elems per thread); n % 4 == 0
__global__ void split4_kernel(const float4* __restrict__ s, int n4,
                              __nv_bfloat162* __restrict__ h,
                              __nv_bfloat162* __restrict__ l)
{
    int i = blockIdx.x * blockDim.x + threadIdx.x;
    if (i >= n4) return;
    float4 v = s[i];
    __nv_bfloat16 hx,lx,hy,ly,hz,lz,hw,lw;
    split2(v.x,hx,lx); split2(v.y,hy,ly); split2(v.z,hz,lz); split2(v.w,hw,lw);
    h[2*i]   = __halves2bfloat162(hx,hy);
    h[2*i+1] = __halves2bfloat162(hz,hw);
    l[2*i]   = __halves2bfloat162(lx,ly);
    l[2*i+1] = __halves2bfloat162(lz,lw);
}

// split with row padding, vec4; out rows_pad x K
__global__ void split_pad_rows4(const float* __restrict__ s, int rows_real, int K,
                                int rows_pad,
                                __nv_bfloat162* __restrict__ h,
                                __nv_bfloat162* __restrict__ l)
{
    int i = blockIdx.x * blockDim.x + threadIdx.x;     // elem4 index
    int n4 = rows_pad * K / 4;
    if (i >= n4) return;
    int r = (i*4) / K;
    float4 v = (r < rows_real) ? *(const float4*)(s + (long)(i*4))
                               : make_float4(0,0,0,0);
    __nv_bfloat16 hx,lx,hy,ly,hz,lz,hw,lw;
    split2(v.x,hx,lx); split2(v.y,hy,ly); split2(v.z,hz,lz); split2(v.w,hw,lw);
    h[2*i]   = __halves2bfloat162(hx,hy);
    h[2*i+1] = __halves2bfloat162(hz,hw);
    l[2*i]   = __halves2bfloat162(lx,ly);
    l[2*i+1] = __halves2bfloat162(lz,lw);
}

// split with col padding (k_take..k_pad zeroed), vec4; k_take%4==0, k_pad%4==0
__global__ void split_pad_cols4(const float* __restrict__ s, int rows, int src_ld,
                                int k_take, int k_pad,
                                __nv_bfloat162* __restrict__ h,
                                __nv_bfloat162* __restrict__ l)
{
    int i = blockIdx.x * blockDim.x + threadIdx.x;
    int n4 = rows * k_pad / 4;
    if (i >= n4) return;
    int kp4 = k_pad / 4;
    int r = i / kp4, k = (i % kp4) * 4;
    float4 v = (k < k_take) ? *(const float4*)(s + (long)r * src_ld + k)
                            : make_float4(0,0,0,0);
    __nv_bfloat16 hx,lx,hy,ly,hz,lz,hw,lw;
    split2(v.x,hx,lx); split2(v.y,hy,ly); split2(v.z,hz,lz); split2(v.w,hw,lw);
    h[2*i]   = __halves2bfloat162(hx,hy);
    h[2*i+1] = __halves2bfloat162(hz,hw);
    l[2*i]   = __halves2bfloat162(lx,ly);
    l[2*i+1] = __halves2bfloat162(lz,lw);
}

// causal depthwise conv(4) + bias + silu + split, 4 channels per thread
__global__ void conv_silu_split_kernel(const float* __restrict__ xr,
                                       const float* __restrict__ cw,
                                       const float* __restrict__ cb,
                                       float* __restrict__ u,
                                       __nv_bfloat162* __restrict__ uh,
                                       __nv_bfloat162* __restrict__ ul)
{
    int i = blockIdx.x * blockDim.x + threadIdx.x;
    if (i >= M_ROWS * D_INNER / 4) return;
    int c = (i*4) % D_INNER;
    int m = (i*4) / D_INNER;
    int l = m % SEQ;
    const float* base = xr + (long)m * (2*D_INNER) + c;
    float4 v0  = *(const float4*)base;
    float4 vm1 = (l >= 1) ? *(const float4*)(base - 1*(2*D_INNER)) : make_float4(0,0,0,0);
    float4 vm2 = (l >= 2) ? *(const float4*)(base - 2*(2*D_INNER)) : make_float4(0,0,0,0);
    float4 vm3 = (l >= 3) ? *(const float4*)(base - 3*(2*D_INNER)) : make_float4(0,0,0,0);
    float4 cbv = *(const float4*)(cb + c);
    const float* p0 = &v0.x; const float* p1 = &vm1.x;
    const float* p2 = &vm2.x; const float* p3 = &vm3.x;
    const float* pb = &cbv.x;
    float o[4];
    #pragma unroll
    for (int t = 0; t < 4; t++) {
        float4 w = *(const float4*)(cw + (c + t) * 4);
        float acc = pb[t] + w.w * p0[t] + w.z * p1[t] + w.y * p2[t] + w.x * p3[t];
        o[t] = acc / (1.f + __expf(-acc));
    }
    *(float4*)(u + (long)i*4) = make_float4(o[0], o[1], o[2], o[3]);
    __nv_bfloat16 hx,lx,hy,ly,hz,lz,hw,lw;
    split2(o[0],hx,lx); split2(o[1],hy,ly); split2(o[2],hz,lz); split2(o[3],hw,lw);
    uh[2*i]   = __halves2bfloat162(hx,hy);
    uh[2*i+1] = __halves2bfloat162(hz,hw);
    ul[2*i]   = __halves2bfloat162(lx,ly);
    ul[2*i+1] = __halves2bfloat162(lz,lw);
}

// reduce split-K=8 x_proj partials (ld 128) -> xdbl (ld 80) + dt-input pad/split
__global__ void reduce_xp_kernel(const float* __restrict__ p,
                                 float* __restrict__ xdbl,
                                 __nv_bfloat16* __restrict__ xdph,
                                 __nv_bfloat16* __restrict__ xdpl)
{
    int i = blockIdx.x * blockDim.x + threadIdx.x;
    if (i >= M_ROWS * 128) return;
    int r = i >> 7, c = i & 127;
    const long S = (long)M_ROWS * 128;
    float s = 0.f;
    #pragma unroll
    for (int z = 0; z < 8; z++) s += p[z*S + i];
    if (c < XDBL_COLS) xdbl[(long)r * XDBL_COLS + c] = s;
    if (c < 64) {
        float v = (c < DT_RANK) ? s : 0.f;
        __nv_bfloat16 h, l; split2(v, h, l);
        xdph[(long)r*64 + c] = h;
        xdpl[(long)r*64 + c] = l;
    }
}

// reduce split-K=4 out_proj partials + residual add into x; vec4
__global__ void reduce_out_kernel(const float* __restrict__ p,
                                  float* __restrict__ x)
{
    int i = blockIdx.x * blockDim.x + threadIdx.x;  // float4 index
    if (i >= M_ROWS * D_MODEL / 4) return;
    const long S4 = (long)M_ROWS * D_MODEL / 4;
    const float4* p4 = (const float4*)p;
    float4 a = ((float4*)x)[i];
    #pragma unroll
    for (int z = 0; z < 4; z++) {
        float4 b = p4[z*S4 + i];
        a.x += b.x; a.y += b.y; a.z += b.z; a.w += b.w;
    }
    ((float4*)x)[i] = a;
}

// selective scan fused: D skip + silu(res) gate + bf16 split of y
__global__ void scan_kernel(const float* __restrict__ delta,
                            const float* __restrict__ u,
                            const float* __restrict__ xdbl,
                            const float* __restrict__ xr,
                            const float* __restrict__ A_log,
                            const float* __restrict__ Dp,
                            __nv_bfloat16* __restrict__ yh,
                            __nv_bfloat16* __restrict__ yl)
{
    int gid  = blockIdx.x * (blockDim.x / 16) + (threadIdx.x / 16);
    int lane = threadIdx.x & 15;
    if (gid >= BATCH * D_INNER) return;
    int b  = gid / D_INNER;
    int di = gid % D_INNER;

    float An = -__expf(A_log[di * D_STATE + lane]);
    float Dv = Dp[di];
    float h  = 0.f;

    long m0 = (long)b * SEQ;
    const float* dptr = delta + m0 * D_INNER + di;
    const float* uptr = u     + m0 * D_INNER + di;
    const float* rptr = xr    + m0 * (2*D_INNER) + D_INNER + di;
    const float* bptr = xdbl  + m0 * XDBL_COLS + DT_RANK + lane;
    const float* cptr = xdbl  + m0 * XDBL_COLS + DT_RANK + D_STATE + lane;

    for (int l = 0; l < SEQ; l++) {
        float dv = dptr[(long)l * D_INNER];
        float uv = uptr[(long)l * D_INNER];
        float Bv = bptr[(long)l * XDBL_COLS];
        float Cv = cptr[(long)l * XDBL_COLS];
        float dA = __expf(dv * An);
        h = fmaf(dA, h, dv * Bv * uv);
        float p = h * Cv;
        p += __shfl_xor_sync(0xffffffffu, p, 8);
        p += __shfl_xor_sync(0xffffffffu, p, 4);
        p += __shfl_xor_sync(0xffffffffu, p, 2);
        p += __shfl_xor_sync(0xffffffffu, p, 1);
        if (lane == 0) {
            float rv = rptr[(long)l * (2*D_INNER)];
            float yv = (p + uv * Dv) * (rv / (1.f + __expf(-rv)));
            __nv_bfloat16 hb, lb; split2(yv, hb, lb);
            yh[m0 * D_INNER + (long)l * D_INNER + di] = hb;
            yl[m0 * D_INNER + (long)l * D_INNER + di] = lb;
        }
    }
}

// ================= mma.sync split-bf16 GEMM =================
// C[M,N] (+z-slice) = (Ah+Al)[M,*] @ (Bh+Bl)[N,*]^T over K window
// [blockIdx.z*klen, +klen), row stride lda. 3-term split, fp32 accum.
// 128x128x32 tiles, 8 warps, 2-stage cp.async, ldmatrix.x4 for A and B.
// mode 0: plain write (C += blockIdx.z*zstride)   mode 1: softplus(acc+ext[col])
#define GPITCH 40

__device__ __forceinline__ uint32_t smem_u32(const void* p) {
    uint32_t a;
    asm("{ .reg .u64 t; cvta.to.shared.u64 t, %1; cvt.u32.u64 %0, t; }" : "=r"(a) : "l"(p));
    return a;
}

#define LDSM_X4(r, addr) \
    asm volatile("ldmatrix.sync.aligned.m8n8.x4.shared.b16 {%0,%1,%2,%3}, [%4];" \
        : "=r"((r)[0]),"=r"((r)[1]),"=r"((r)[2]),"=r"((r)[3]) : "r"(addr))

#define MMA_BF16(c, a, b) \
    asm volatile("mma.sync.aligned.m16n8k16.row.col.f32.bf16.bf16.f32 " \
        "{%0,%1,%2,%3},{%4,%5,%6,%7},{%8,%9},{%0,%1,%2,%3};" \
        : "+f"((c)[0]),"+f"((c)[1]),"+f"((c)[2]),"+f"((c)[3]) \
        : "r"((a)[0]),"r"((a)[1]),"r"((a)[2]),"r"((a)[3]),"r"((b)[0]),"r"((b)[1]))

#define CP16(dst, src) \
    asm volatile("cp.async.cg.shared.global [%0], [%1], 16;" :: "r"(dst), "l"(src))
#define CP_COMMIT() asm volatile("cp.async.commit_group;" ::: "memory")
#define CP_WAIT(n)  asm volatile("cp.async.wait_group %0;" :: "n"(n) : "memory")

#define STAGE_ELEMS (512 * GPITCH)
#define GSMEM_BYTES (2 * STAGE_ELEMS * 2)    // 81920 B

__global__ void __launch_bounds__(256, 2) mma_gemm(
    const __nv_bfloat16* __restrict__ Ah, const __nv_bfloat16* __restrict__ Al,
    const __nv_bfloat16* __restrict__ Bh, const __nv_bfloat16* __restrict__ Bl,
    int lda, int klen,
    float* __restrict__ C, int ldc, int Nreal,
    const float* __restrict__ ext, int mode, long zstride)
{
    extern __shared__ __nv_bfloat16 sm[];
    const uint32_t sbase = smem_u32(sm);
    const int tid  = threadIdx.x;
    const int lane = tid & 31;
    const int w    = tid >> 5;
    const int wm   = (w >> 2) << 6;
    const int wn   = (w & 3) << 5;
    const long bm  = (long)blockIdx.y * 128;
    const long bn  = (long)blockIdx.x * 128;
    const int koff = blockIdx.z * klen;
    C += (long)blockIdx.z * zstride;

    float acc[4][4][4];
    #pragma unroll
    for (int i = 0; i < 4; i++)
        #pragma unroll
        for (int j = 0; j < 4; j++)
            #pragma unroll
            for (int e = 0; e < 4; e++) acc[i][j][e] = 0.f;

    const int NC = klen >> 5;

    #define LOAD_STAGE(st, kc) do {                                           \
        int _k0 = koff + ((kc) << 5);                                         \
        _Pragma("unroll")                                                     \
        for (int _it = 0; _it < 8; _it++) {                                   \
            int _i = _it * 256 + tid;                                         \
            int _rg = _i >> 2, _ch = _i & 3;                                  \
            const __nv_bfloat16* _gb; long _grow;                             \
            if (_rg < 256) {                                                  \
                int _a = _rg >= 128;                                          \
                _gb = _a ? Al : Ah; _grow = bm + (_rg - _a * 128);            \
            } else {                                                          \
                int _rb = _rg - 256;                                          \
                int _a = _rb >= 128;                                          \
                _gb = _a ? Bl : Bh; _grow = bn + (_rb - _a * 128);            \
            }                                                                 \
            const void* _src = _gb + _grow * (long)lda + _k0 + _ch * 8;       \
            uint32_t _dst = sbase + ((st) * STAGE_ELEMS + _rg * GPITCH        \
                                     + _ch * 8) * 2;                          \
            CP16(_dst, _src);                                                 \
        }                                                                     \
        CP_COMMIT();                                                          \
    } while (0)

    LOAD_STAGE(0, 0);
    LOAD_STAGE(1, 1);

    for (int c = 0; c < NC; c++) {
        if (c + 1 < NC) CP_WAIT(1);
        else            CP_WAIT(0);
        __syncthreads();

        const int s = c & 1;
        const uint32_t stg = sbase + (s * STAGE_ELEMS) * 2;
        const uint32_t aH = stg;
        const uint32_t aL = stg + (128 * GPITCH) * 2;
        const uint32_t bH = stg + (256 * GPITCH) * 2;
        const uint32_t bL = stg + (384 * GPITCH) * 2;

        #pragma unroll
        for (int ks = 0; ks < 2; ks++) {
            const int k0 = ks << 4;
            const uint32_t aoff = ((wm + (lane & 15)) * GPITCH
                                   + k0 + ((lane >> 4) << 3)) * 2;
            const int brow = wn + (lane & 7) + ((lane >> 4) << 3);
            const uint32_t boff = (brow * GPITCH + k0 + (((lane >> 3) & 1) << 3)) * 2;

            uint32_t ah[4][4], al[4][4];
            uint32_t bhf[2][4], blf[2][4];
            #pragma unroll
            for (int mi = 0; mi < 4; mi++)
                LDSM_X4(ah[mi], aH + aoff + mi * 16 * GPITCH * 2);
            LDSM_X4(bhf[0], bH + boff);
            LDSM_X4(bhf[1], bH + boff + 16 * GPITCH * 2);
            #pragma unroll
            for (int mi = 0; mi < 4; mi++)
                #pragma unroll
                for (int ni = 0; ni < 4; ni++)
                    MMA_BF16(acc[mi][ni], ah[mi], &bhf[ni>>1][(ni&1)<<1]);

            LDSM_X4(blf[0], bL + boff);
            LDSM_X4(blf[1], bL + boff + 16 * GPITCH * 2);
            #pragma unroll
            for (int mi = 0; mi < 4; mi++)
                #pragma unroll
                for (int ni = 0; ni < 4; ni++)
                    MMA_BF16(acc[mi][ni], ah[mi], &blf[ni>>1][(ni&1)<<1]);

            #pragma unroll
            for (int mi = 0; mi < 4; mi++)
                LDSM_X4(al[mi], aL + aoff + mi * 16 * GPITCH * 2);
            #pragma unroll
            for (int mi = 0; mi < 4; mi++)
                #pragma unroll
                for (int ni = 0; ni < 4; ni++)
                    MMA_BF16(acc[mi][ni], al[mi], &bhf[ni>>1][(ni&1)<<1]);
        }
        __syncthreads();
        if (c + 2 < NC) LOAD_STAGE(s, c + 2);
    }
    #undef LOAD_STAGE

    // ---- epilogue ----
    const int g  = lane >> 2;
    const int cc = (lane & 3) << 1;
    #pragma unroll
    for (int mi = 0; mi < 4; mi++) {
        #pragma unroll
        for (int ni = 0; ni < 4; ni++) {
            int col = (int)bn + wn + ni * 8 + cc;
            if (col >= Nreal) continue;
            long row0 = bm + wm + mi * 16 + g;
            float v0 = acc[mi][ni][0], v1 = acc[mi][ni][1];
            float v2 = acc[mi][ni][2], v3 = acc[mi][ni][3];
            if (mode == 1) {
                float b0 = ext[col], b1 = ext[col + 1];
                v0 += b0; v1 += b1; v2 += b0; v3 += b1;
                v0 = (v0 > 20.f) ? v0 : log1pf(__expf(v0));
                v1 = (v1 > 20.f) ? v1 : log1pf(__expf(v1));
                v2 = (v2 > 20.f) ? v2 : log1pf(__expf(v2));
                v3 = (v3 > 20.f) ? v3 : log1pf(__expf(v3));
            }
            *(float2*)(C + row0 * ldc + col)       = make_float2(v0, v1);
            *(float2*)(C + (row0 + 8) * ldc + col) = make_float2(v2, v3);
        }
    }
}

// ================= launch =================
extern "C" void kernel_launch(void* const* d_in, const int* in_sizes, int n_in,
                              void* d_out, int out_size)
{
    const int*   ids    = (const int*)  d_in[0];
    const float* emb    = (const float*)d_in[1];
    const float* normw  = (const float*)d_in[2];
    const float* inpw   = (const float*)d_in[3];
    const float* convw  = (const float*)d_in[4];
    const float* convb  = (const float*)d_in[5];
    const float* xprojw = (const float*)d_in[6];
    const float* dtpw   = (const float*)d_in[7];
    const float* dtpb   = (const float*)d_in[8];
    const float* Alog   = (const float*)d_in[9];
    const float* Dw     = (const float*)d_in[10];
    const float* outpw  = (const float*)d_in[11];
    const float* normf  = (const float*)d_in[12];
    float* out = (float*)d_out;

    float *x, *xr, *u, *xdbl, *delta, *part;
    cudaGetSymbolAddress((void**)&x,     g_x);
    cudaGetSymbolAddress((void**)&xr,    g_xr);
    cudaGetSymbolAddress((void**)&u,     g_u);
    cudaGetSymbolAddress((void**)&xdbl,  g_xdbl);
    cudaGetSymbolAddress((void**)&delta, g_delta);
    cudaGetSymbolAddress((void**)&part,  g_part);

    __nv_bfloat16 *emb_h, *emb_l, *inpw_h, *inpw_l, *outpw_h, *outpw_l;
    __nv_bfloat16 *xn_h, *xn_l, *u_h, *u_l, *y_h, *y_l;
    __nv_bfloat16 *xpw_h, *xpw_l, *dtw_h, *dtw_l, *xdp_h, *xdp_l;
    cudaGetSymbolAddress((void**)&emb_h,  g_emb_h);   cudaGetSymbolAddress((void**)&emb_l,  g_emb_l);
    cudaGetSymbolAddress((void**)&inpw_h, g_inpw_h);  cudaGetSymbolAddress((void**)&inpw_l, g_inpw_l);
    cudaGetSymbolAddress((void**)&outpw_h,g_outpw_h); cudaGetSymbolAddress((void**)&outpw_l,g_outpw_l);
    cudaGetSymbolAddress((void**)&xn_h,   g_xn_h);    cudaGetSymbolAddress((void**)&xn_l,   g_xn_l);
    cudaGetSymbolAddress((void**)&u_h,    g_u_h);     cudaGetSymbolAddress((void**)&u_l,    g_u_l);
    cudaGetSymbolAddress((void**)&y_h,    g_y_h);     cudaGetSymbolAddress((void**)&y_l,    g_y_l);
    cudaGetSymbolAddress((void**)&xpw_h,  g_xpw_h);   cudaGetSymbolAddress((void**)&xpw_l,  g_xpw_l);
    cudaGetSymbolAddress((void**)&dtw_h,  g_dtw_h);   cudaGetSymbolAddress((void**)&dtw_l,  g_dtw_l);
    cudaGetSymbolAddress((void**)&xdp_h,  g_xdp_h);   cudaGetSymbolAddress((void**)&xdp_l,  g_xdp_l);

    cudaFuncSetAttribute(mma_gemm, cudaFuncAttributeMaxDynamicSharedMemorySize,
                         GSMEM_BYTES);

    #define SPLIT4(src, n, h, l) \
        split4_kernel<<<((n)/4 + 255) / 256, 256>>>((const float4*)(src), (n)/4, \
            (__nv_bfloat162*)(h), (__nv_bfloat162*)(l))

    // launch order keeps in_proj as the 4th launch (ncu capture window)
    embed_kernel<<<M_ROWS, 256>>>(ids, emb, x);                               // 1
    SPLIT4(inpw, N_LAYER * 2 * D_INNER * D_MODEL, inpw_h, inpw_l);            // 2

    for (int lyr = 0; lyr < N_LAYER; lyr++) {
        rmsnorm_split_kernel<<<M_ROWS, 256>>>(x, normw + lyr * D_MODEL,
                                              xn_h, xn_l);                    // 3

        // in_proj: (2048,768) @ (3072,768)^T -> xr                           // 4 (profiled)
        mma_gemm<<<dim3(2*D_INNER/128, M_ROWS/128, 1), 256, GSMEM_BYTES>>>(
            xn_h, xn_l,
            inpw_h + (long)lyr * 2*D_INNER*D_MODEL,
            inpw_l + (long)lyr * 2*D_INNER*D_MODEL,
            D_MODEL, D_MODEL, xr, 2*D_INNER, 2*D_INNER, nullptr, 0, 0);

        conv_silu_split_kernel<<<(M_ROWS*D_INNER/4 + 255)/256, 256>>>(
            xr, convw + lyr * D_INNER*D_CONV, convb + lyr * D_INNER,
            u, (__nv_bfloat162*)u_h, (__nv_bfloat162*)u_l);

        {
            int n4 = 128 * D_INNER / 4;
            split_pad_rows4<<<(n4 + 255)/256, 256>>>(
                xprojw + (long)lyr * XDBL_COLS * D_INNER, XDBL_COLS, D_INNER, 128,
                (__nv_bfloat162*)xpw_h, (__nv_bfloat162*)xpw_l);
        }
        // x_proj split-K=8: (2048,1536/8 per z) @ (128,1536)^T -> partials
        mma_gemm<<<dim3(1, M_ROWS/128, 8), 256, GSMEM_BYTES>>>(
            u_h, u_l, xpw_h, xpw_l,
            D_INNER, D_INNER/8, part, 128, 128, nullptr, 0, (long)M_ROWS*128);
        reduce_xp_kernel<<<(M_ROWS*128 + 255)/256, 256>>>(part, xdbl, xdp_h, xdp_l);

        {
            int n4 = D_INNER * 64 / 4;
            split_pad_cols4<<<(n4 + 255)/256, 256>>>(
                dtpw + (long)lyr * D_INNER * DT_RANK, D_INNER, DT_RANK,
                DT_RANK, 64, (__nv_bfloat162*)dtw_h, (__nv_bfloat162*)dtw_l);
        }
        // dt_proj (K=64) + bias + softplus -> delta
        mma_gemm<<<dim3(D_INNER/128, M_ROWS/128, 1), 256, GSMEM_BYTES>>>(
            xdp_h, xdp_l, dtw_h, dtw_l,
            64, 64, delta, D_INNER, D_INNER, dtpb + lyr * D_INNER, 1, 0);

        // selective scan (writes y split directly)
        scan_kernel<<<(BATCH*D_INNER)/16, 256>>>(
            delta, u, xdbl, xr, Alog + (long)lyr * D_INNER*D_STATE,
            Dw + lyr * D_INNER, y_h, y_l);

        if (lyr == 0)
            SPLIT4(outpw, N_LAYER * D_MODEL * D_INNER, outpw_h, outpw_l);

        // out_proj split-K=4 -> partials; reduce adds residual into x
        mma_gemm<<<dim3(D_MODEL/128, M_ROWS/128, 4), 256, GSMEM_BYTES>>>(
            y_h, y_l,
            outpw_h + (long)lyr * D_MODEL*D_INNER,
            outpw_l + (long)lyr * D_MODEL*D_INNER,
            D_INNER, D_INNER/4, part, D_MODEL, D_MODEL, nullptr, 0,
            (long)M_ROWS*D_MODEL);
        reduce_out_kernel<<<(M_ROWS*D_MODEL/4 + 255)/256, 256>>>(part, x);
    }

    SPLIT4(emb, VOCAB * D_MODEL, emb_h, emb_l);
    rmsnorm_split_kernel<<<M_ROWS, 256>>>(x, normf, xn_h, xn_l);

    // logits: (2048,768) @ (32000,768)^T -> out
    mma_gemm<<<dim3(VOCAB/128, M_ROWS/128, 1), 256, GSMEM_BYTES>>>(
        xn_h, xn_l, emb_h, emb_l,
        D_MODEL, D_MODEL, out, VOCAB, VOCAB, nullptr, 0, 0);
}

// round 7
// speedup vs baseline: 1.6860x; 1.5508x over previous
#include <cuda_runtime.h>
#include <cuda_fp16.h>
#include <math.h>
#include <stdint.h>

// ---------------- model dims ----------------
#define BATCH      2
#define SEQ        1024
#define M_ROWS     (BATCH*SEQ)        // 2048
#define D_MODEL    768
#define D_INNER    1536
#define D_STATE    16
#define DT_RANK    48
#define D_CONV     4
#define XDBL_COLS  (DT_RANK + 2*D_STATE)   // 80
#define VOCAB      32000
#define N_LAYER    2
#define EPS        1e-5f

// ---------------- fp32 scratch ----------------
__device__ __align__(16) float g_x    [M_ROWS * D_MODEL];
__device__ __align__(16) float g_xr   [M_ROWS * 2 * D_INNER];
__device__ __align__(16) float g_u    [M_ROWS * D_INNER];
__device__ __align__(16) float g_xdbl [M_ROWS * XDBL_COLS];
__device__ __align__(16) float g_delta[M_ROWS * D_INNER];
__device__ __align__(16) float g_part [4 * M_ROWS * D_MODEL];

// ---------------- fp16 hi/lo split buffers ----------------
__device__ __align__(16) __half g_emb_h [VOCAB*D_MODEL];
__device__ __align__(16) __half g_emb_l [VOCAB*D_MODEL];
__device__ __align__(16) __half g_inpw_h[N_LAYER*2*D_INNER*D_MODEL];
__device__ __align__(16) __half g_inpw_l[N_LAYER*2*D_INNER*D_MODEL];
__device__ __align__(16) __half g_outpw_h[N_LAYER*D_MODEL*D_INNER];
__device__ __align__(16) __half g_outpw_l[N_LAYER*D_MODEL*D_INNER];
__device__ __align__(16) __half g_xn_h[M_ROWS*D_MODEL];
__device__ __align__(16) __half g_xn_l[M_ROWS*D_MODEL];
__device__ __align__(16) __half g_u_h [M_ROWS*D_INNER];
__device__ __align__(16) __half g_u_l [M_ROWS*D_INNER];
__device__ __align__(16) __half g_y_h [M_ROWS*D_INNER];
__device__ __align__(16) __half g_y_l [M_ROWS*D_INNER];
__device__ __align__(16) __half g_xpw_h[128*D_INNER];
__device__ __align__(16) __half g_xpw_l[128*D_INNER];
__device__ __align__(16) __half g_dtw_h[D_INNER*64];
__device__ __align__(16) __half g_dtw_l[D_INNER*64];
__device__ __align__(16) __half g_xdp_h[M_ROWS*64];
__device__ __align__(16) __half g_xdp_l[M_ROWS*64];

// ================= helpers =================
__device__ __forceinline__ void split2(float v, __half& h, __half& l) {
    h = __float2half_rn(v);
    l = __float2half_rn(v - __half2float(h));
}

// ================= small kernels =================
__global__ void embed_kernel(const int* __restrict__ ids,
                             const float* __restrict__ emb,
                             float* __restrict__ x)
{
    int row = blockIdx.x;
    int tok = ids[row];
    const float4* src = (const float4*)(emb + (long)tok * D_MODEL);
    float4* dst = (float4*)(x + (long)row * D_MODEL);
    for (int i = threadIdx.x; i < D_MODEL/4; i += blockDim.x) dst[i] = src[i];
}

__global__ void rmsnorm_split_kernel(const float* __restrict__ x,
                                     const float* __restrict__ w,
                                     __half* __restrict__ oh,
                                     __half* __restrict__ ol)
{
    __shared__ float red[8];
    int row = blockIdx.x;
    const float* xp = x + (long)row * D_MODEL;
    float s = 0.f;
    for (int i = threadIdx.x; i < D_MODEL; i += 256) { float v = xp[i]; s += v*v; }
    #pragma unroll
    for (int o = 16; o; o >>= 1) s += __shfl_xor_sync(0xffffffffu, s, o);
    if ((threadIdx.x & 31) == 0) red[threadIdx.x >> 5] = s;
    __syncthreads();
    if (threadIdx.x < 8) {
        float t = red[threadIdx.x];
        #pragma unroll
        for (int o = 4; o; o >>= 1) t += __shfl_xor_sync(0xffu, t, o);
        if (threadIdx.x == 0) red[0] = t;
    }
    __syncthreads();
    float scale = rsqrtf(red[0] / (float)D_MODEL + EPS);
    for (int i = threadIdx.x; i < D_MODEL; i += 256) {
        float v = xp[i] * scale * w[i];
        __half h, l; split2(v, h, l);
        oh[(long)row * D_MODEL + i] = h;
        ol[(long)row * D_MODEL + i] = l;
    }
}

__global__ void split4_kernel(const float4* __restrict__ s, int n4,
                              __half2* __restrict__ h, __half2* __restrict__ l)
{
    int i = blockIdx.x * blockDim.x + threadIdx.x;
    if (i >= n4) return;
    float4 v = s[i];
    __half hx,lx,hy,ly,hz,lz,hw,lw;
    split2(v.x,hx,lx); split2(v.y,hy,ly); split2(v.z,hz,lz); split2(v.w,hw,lw);
    h[2*i]   = __halves2half2(hx,hy);
    h[2*i+1] = __halves2half2(hz,hw);
    l[2*i]   = __halves2half2(lx,ly);
    l[2*i+1] = __halves2half2(lz,lw);
}

__global__ void split_pad_rows4(const float* __restrict__ s, int rows_real, int K,
                                int rows_pad,
                                __half2* __restrict__ h, __half2* __restrict__ l)
{
    int i = blockIdx.x * blockDim.x + threadIdx.x;
    int n4 = rows_pad * K / 4;
    if (i >= n4) return;
    int r = (i*4) / K;
    float4 v = (r < rows_real) ? *(const float4*)(s + (long)(i*4))
                               : make_float4(0,0,0,0);
    __half hx,lx,hy,ly,hz,lz,hw,lw;
    split2(v.x,hx,lx); split2(v.y,hy,ly); split2(v.z,hz,lz); split2(v.w,hw,lw);
    h[2*i]   = __halves2half2(hx,hy);
    h[2*i+1] = __halves2half2(hz,hw);
    l[2*i]   = __halves2half2(lx,ly);
    l[2*i+1] = __halves2half2(lz,lw);
}

__global__ void split_pad_cols4(const float* __restrict__ s, int rows, int src_ld,
                                int k_take, int k_pad,
                                __half2* __restrict__ h, __half2* __restrict__ l)
{
    int i = blockIdx.x * blockDim.x + threadIdx.x;
    int n4 = rows * k_pad / 4;
    if (i >= n4) return;
    int kp4 = k_pad / 4;
    int r = i / kp4, k = (i % kp4) * 4;
    float4 v = (k < k_take) ? *(const float4*)(s + (long)r * src_ld + k)
                            : make_float4(0,0,0,0);
    __half hx,lx,hy,ly,hz,lz,hw,lw;
    split2(v.x,hx,lx); split2(v.y,hy,ly); split2(v.z,hz,lz); split2(v.w,hw,lw);
    h[2*i]   = __halves2half2(hx,hy);
    h[2*i+1] = __halves2half2(hz,hw);
    l[2*i]   = __halves2half2(lx,ly);
    l[2*i+1] = __halves2half2(lz,lw);
}

__global__ void conv_silu_split_kernel(const float* __restrict__ xr,
                                       const float* __restrict__ cw,
                                       const float* __restrict__ cb,
                                       float* __restrict__ u,
                                       __half2* __restrict__ uh,
                                       __half2* __restrict__ ul)
{
    int i = blockIdx.x * blockDim.x + threadIdx.x;
    if (i >= M_ROWS * D_INNER / 4) return;
    int c = (i*4) % D_INNER;
    int m = (i*4) / D_INNER;
    int l = m % SEQ;
    const float* base = xr + (long)m * (2*D_INNER) + c;
    float4 v0  = *(const float4*)base;
    float4 vm1 = (l >= 1) ? *(const float4*)(base - 1*(2*D_INNER)) : make_float4(0,0,0,0);
    float4 vm2 = (l >= 2) ? *(const float4*)(base - 2*(2*D_INNER)) : make_float4(0,0,0,0);
    float4 vm3 = (l >= 3) ? *(const float4*)(base - 3*(2*D_INNER)) : make_float4(0,0,0,0);
    float4 cbv = *(const float4*)(cb + c);
    const float* p0 = &v0.x; const float* p1 = &vm1.x;
    const float* p2 = &vm2.x; const float* p3 = &vm3.x;
    const float* pb = &cbv.x;
    float o[4];
    #pragma unroll
    for (int t = 0; t < 4; t++) {
        float4 w = *(const float4*)(cw + (c + t) * 4);
        float acc = pb[t] + w.w * p0[t] + w.z * p1[t] + w.y * p2[t] + w.x * p3[t];
        o[t] = acc / (1.f + __expf(-acc));
    }
    *(float4*)(u + (long)i*4) = make_float4(o[0], o[1], o[2], o[3]);
    __half hx,lx,hy,ly,hz,lz,hw,lw;
    split2(o[0],hx,lx); split2(o[1],hy,ly); split2(o[2],hz,lz); split2(o[3],hw,lw);
    uh[2*i]   = __halves2half2(hx,hy);
    uh[2*i+1] = __halves2half2(hz,hw);
    ul[2*i]   = __halves2half2(lx,ly);
    ul[2*i+1] = __halves2half2(lz,lw);
}

__global__ void reduce_xp_kernel(const float* __restrict__ p,
                                 float* __restrict__ xdbl,
                                 __half* __restrict__ xdph,
                                 __half* __restrict__ xdpl)
{
    int i = blockIdx.x * blockDim.x + threadIdx.x;
    if (i >= M_ROWS * 128) return;
    int r = i >> 7, c = i & 127;
    const long S = (long)M_ROWS * 128;
    float s = 0.f;
    #pragma unroll
    for (int z = 0; z < 8; z++) s += p[z*S + i];
    if (c < XDBL_COLS) xdbl[(long)r * XDBL_COLS + c] = s;
    if (c < 64) {
        float v = (c < DT_RANK) ? s : 0.f;
        __half h, l; split2(v, h, l);
        xdph[(long)r*64 + c] = h;
        xdpl[(long)r*64 + c] = l;
    }
}

__global__ void reduce_out_kernel(const float* __restrict__ p,
                                  float* __restrict__ x)
{
    int i = blockIdx.x * blockDim.x + threadIdx.x;
    if (i >= M_ROWS * D_MODEL / 4) return;
    const long S4 = (long)M_ROWS * D_MODEL / 4;
    const float4* p4 = (const float4*)p;
    float4 a = ((float4*)x)[i];
    #pragma unroll
    for (int z = 0; z < 4; z++) {
        float4 b = p4[z*S4 + i];
        a.x += b.x; a.y += b.y; a.z += b.z; a.w += b.w;
    }
    ((float4*)x)[i] = a;
}

// selective scan: software-pipelined loads; D skip + silu gate + fp16 split
__global__ void scan_kernel(const float* __restrict__ delta,
                            const float* __restrict__ u,
                            const float* __restrict__ xdbl,
                            const float* __restrict__ xr,
                            const float* __restrict__ A_log,
                            const float* __restrict__ Dp,
                            __half* __restrict__ yh,
                            __half* __restrict__ yl)
{
    int gid  = blockIdx.x * (blockDim.x / 16) + (threadIdx.x / 16);
    int lane = threadIdx.x & 15;
    if (gid >= BATCH * D_INNER) return;
    int b  = gid / D_INNER;
    int di = gid % D_INNER;

    float An = -__expf(A_log[di * D_STATE + lane]);
    float Dv = Dp[di];
    float h  = 0.f;

    long m0 = (long)b * SEQ;
    const float* dptr = delta + m0 * D_INNER + di;
    const float* uptr = u     + m0 * D_INNER + di;
    const float* rptr = xr    + m0 * (2*D_INNER) + D_INNER + di;
    const float* bptr = xdbl  + m0 * XDBL_COLS + DT_RANK + lane;
    const float* cptr = xdbl  + m0 * XDBL_COLS + DT_RANK + D_STATE + lane;
    __half* yhp = yh + m0 * D_INNER + di;
    __half* ylp = yl + m0 * D_INNER + di;

    // prefetched registers for current iteration
    float dv = dptr[0], uv = uptr[0], Bv = bptr[0], Cv = cptr[0], rv = rptr[0];

    for (int l = 0; l < SEQ; l++) {
        float dv_n, uv_n, Bv_n, Cv_n, rv_n;
        if (l + 1 < SEQ) {
            long ln = l + 1;
            dv_n = dptr[ln * D_INNER];
            uv_n = uptr[ln * D_INNER];
            Bv_n = bptr[ln * XDBL_COLS];
            Cv_n = cptr[ln * XDBL_COLS];
            rv_n = rptr[ln * (2*D_INNER)];
        } else { dv_n = uv_n = Bv_n = Cv_n = rv_n = 0.f; }

        float dA = __expf(dv * An);
        h = fmaf(dA, h, dv * Bv * uv);
        float p = h * Cv;
        p += __shfl_xor_sync(0xffffffffu, p, 8);
        p += __shfl_xor_sync(0xffffffffu, p, 4);
        p += __shfl_xor_sync(0xffffffffu, p, 2);
        p += __shfl_xor_sync(0xffffffffu, p, 1);
        if (lane == 0) {
            float yv = (p + uv * Dv) * (rv / (1.f + __expf(-rv)));
            __half hb, lb; split2(yv, hb, lb);
            yhp[(long)l * D_INNER] = hb;
            ylp[(long)l * D_INNER] = lb;
        }
        dv = dv_n; uv = uv_n; Bv = Bv_n; Cv = Cv_n; rv = rv_n;
    }
}

// ================= mma.sync split-fp16 GEMM =================
// TERMS=3: D = Ah*Bh + Ah*Bl + Al*Bh    TERMS=2: D = Ah*Bh + Al*Bh (= A*Bh;
//          Bl never loaded -> 25% less stage traffic)
// fp32 accum. 128x128x32 tiles, 8 warps, 2-stage cp.async, ldmatrix.x4.
// mode 0: plain (C += z*zstride)   mode 1: softplus(acc + ext[col])
#define GPITCH 40

__device__ __forceinline__ uint32_t smem_u32(const void* p) {
    uint32_t a;
    asm("{ .reg .u64 t; cvta.to.shared.u64 t, %1; cvt.u32.u64 %0, t; }" : "=r"(a) : "l"(p));
    return a;
}

#define LDSM_X4(r, addr) \
    asm volatile("ldmatrix.sync.aligned.m8n8.x4.shared.b16 {%0,%1,%2,%3}, [%4];" \
        : "=r"((r)[0]),"=r"((r)[1]),"=r"((r)[2]),"=r"((r)[3]) : "r"(addr))

#define MMA_F16(c, a, b) \
    asm volatile("mma.sync.aligned.m16n8k16.row.col.f32.f16.f16.f32 " \
        "{%0,%1,%2,%3},{%4,%5,%6,%7},{%8,%9},{%0,%1,%2,%3};" \
        : "+f"((c)[0]),"+f"((c)[1]),"+f"((c)[2]),"+f"((c)[3]) \
        : "r"((a)[0]),"r"((a)[1]),"r"((a)[2]),"r"((a)[3]),"r"((b)[0]),"r"((b)[1]))

#define CP16(dst, src) \
    asm volatile("cp.async.cg.shared.global [%0], [%1], 16;" :: "r"(dst), "l"(src))
#define CP_COMMIT() asm volatile("cp.async.commit_group;" ::: "memory")
#define CP_WAIT(n)  asm volatile("cp.async.wait_group %0;" :: "n"(n) : "memory")

#define STAGE_ELEMS (512 * GPITCH)
#define GSMEM_BYTES (2 * STAGE_ELEMS * 2)    // 81920 B

template<int TERMS>
__global__ void __launch_bounds__(256, 2) mma_gemm(
    const __half* __restrict__ Ah, const __half* __restrict__ Al,
    const __half* __restrict__ Bh, const __half* __restrict__ Bl,
    int lda, int klen,
    float* __restrict__ C, int ldc, int Nreal,
    const float* __restrict__ ext, int mode, long zstride)
{
    extern __shared__ __half sm[];
    const uint32_t sbase = smem_u32(sm);
    const int tid  = threadIdx.x;
    const int lane = tid & 31;
    const int w    = tid >> 5;
    const int wm   = (w >> 2) << 6;
    const int wn   = (w & 3) << 5;
    const long bm  = (long)blockIdx.y * 128;
    const long bn  = (long)blockIdx.x * 128;
    const int koff = blockIdx.z * klen;
    C += (long)blockIdx.z * zstride;

    float acc[4][4][4];
    #pragma unroll
    for (int i = 0; i < 4; i++)
        #pragma unroll
        for (int j = 0; j < 4; j++)
            #pragma unroll
            for (int e = 0; e < 4; e++) acc[i][j][e] = 0.f;

    const int NC = klen >> 5;

    #define LOAD_STAGE(st, kc) do {                                           \
        int _k0 = koff + ((kc) << 5);                                         \
        _Pragma("unroll")                                                     \
        for (int _it = 0; _it < 8; _it++) {                                   \
            int _i = _it * 256 + tid;                                         \
            int _rg = _i >> 2, _ch = _i & 3;                                  \
            if (TERMS == 2 && _rg >= 384) continue;   /* skip Bl */           \
            const __half* _gb; long _grow;                                    \
            if (_rg < 256) {                                                  \
                int _a = _rg >= 128;                                          \
                _gb = _a ? Al : Ah; _grow = bm + (_rg - _a * 128);            \
            } else {                                                          \
                int _rb = _rg - 256;                                          \
                int _a = _rb >= 128;                                          \
                _gb = _a ? Bl : Bh; _grow = bn + (_rb - _a * 128);            \
            }                                                                 \
            const void* _src = _gb + _grow * (long)lda + _k0 + _ch * 8;       \
            uint32_t _dst = sbase + ((st) * STAGE_ELEMS + _rg * GPITCH        \
                                     + _ch * 8) * 2;                          \
            CP16(_dst, _src);                                                 \
        }                                                                     \
        CP_COMMIT();                                                          \
    } while (0)

    LOAD_STAGE(0, 0);
    LOAD_STAGE(1, 1);

    for (int c = 0; c < NC; c++) {
        if (c + 1 < NC) CP_WAIT(1);
        else            CP_WAIT(0);
        __syncthreads();

        const int s = c & 1;
        const uint32_t stg = sbase + (s * STAGE_ELEMS) * 2;
        const uint32_t aH = stg;
        const uint32_t aL = stg + (128 * GPITCH) * 2;
        const uint32_t bH = stg + (256 * GPITCH) * 2;
        const uint32_t bL = stg + (384 * GPITCH) * 2;

        #pragma unroll
        for (int ks = 0; ks < 2; ks++) {
            const int k0 = ks << 4;
            const uint32_t aoff = ((wm + (lane & 15)) * GPITCH
                                   + k0 + ((lane >> 4) << 3)) * 2;
            const int brow = wn + (lane & 7) + ((lane >> 4) << 3);
            const uint32_t boff = (brow * GPITCH + k0 + (((lane >> 3) & 1) << 3)) * 2;

            uint32_t ah[4][4], al[4][4];
            uint32_t bhf[2][4];
            #pragma unroll
            for (int mi = 0; mi < 4; mi++)
                LDSM_X4(ah[mi], aH + aoff + mi * 16 * GPITCH * 2);
            LDSM_X4(bhf[0], bH + boff);
            LDSM_X4(bhf[1], bH + boff + 16 * GPITCH * 2);
            #pragma unroll
            for (int mi = 0; mi < 4; mi++)
                #pragma unroll
                for (int ni = 0; ni < 4; ni++)
                    MMA_F16(acc[mi][ni], ah[mi], &bhf[ni>>1][(ni&1)<<1]);

            if (TERMS == 3) {
                uint32_t blf[2][4];
                LDSM_X4(blf[0], bL + boff);
                LDSM_X4(blf[1], bL + boff + 16 * GPITCH * 2);
                #pragma unroll
                for (int mi = 0; mi < 4; mi++)
                    #pragma unroll
                    for (int ni = 0; ni < 4; ni++)
                        MMA_F16(acc[mi][ni], ah[mi], &blf[ni>>1][(ni&1)<<1]);
            }

            #pragma unroll
            for (int mi = 0; mi < 4; mi++)
                LDSM_X4(al[mi], aL + aoff + mi * 16 * GPITCH * 2);
            #pragma unroll
            for (int mi = 0; mi < 4; mi++)
                #pragma unroll
                for (int ni = 0; ni < 4; ni++)
                    MMA_F16(acc[mi][ni], al[mi], &bhf[ni>>1][(ni&1)<<1]);
        }
        __syncthreads();
        if (c + 2 < NC) LOAD_STAGE(s, c + 2);
    }
    #undef LOAD_STAGE

    // ---- epilogue ----
    const int g  = lane >> 2;
    const int cc = (lane & 3) << 1;
    #pragma unroll
    for (int mi = 0; mi < 4; mi++) {
        #pragma unroll
        for (int ni = 0; ni < 4; ni++) {
            int col = (int)bn + wn + ni * 8 + cc;
            if (col >= Nreal) continue;
            long row0 = bm + wm + mi * 16 + g;
            float v0 = acc[mi][ni][0], v1 = acc[mi][ni][1];
            float v2 = acc[mi][ni][2], v3 = acc[mi][ni][3];
            if (mode == 1) {
                float b0 = ext[col], b1 = ext[col + 1];
                v0 += b0; v1 += b1; v2 += b0; v3 += b1;
                v0 = (v0 > 20.f) ? v0 : log1pf(__expf(v0));
                v1 = (v1 > 20.f) ? v1 : log1pf(__expf(v1));
                v2 = (v2 > 20.f) ? v2 : log1pf(__expf(v2));
                v3 = (v3 > 20.f) ? v3 : log1pf(__expf(v3));
            }
            *(float2*)(C + row0 * ldc + col)       = make_float2(v0, v1);
            *(float2*)(C + (row0 + 8) * ldc + col) = make_float2(v2, v3);
        }
    }
}

// ================= launch =================
extern "C" void kernel_launch(void* const* d_in, const int* in_sizes, int n_in,
                              void* d_out, int out_size)
{
    const int*   ids    = (const int*)  d_in[0];
    const float* emb    = (const float*)d_in[1];
    const float* normw  = (const float*)d_in[2];
    const float* inpw   = (const float*)d_in[3];
    const float* convw  = (const float*)d_in[4];
    const float* convb  = (const float*)d_in[5];
    const float* xprojw = (const float*)d_in[6];
    const float* dtpw   = (const float*)d_in[7];
    const float* dtpb   = (const float*)d_in[8];
    const float* Alog   = (const float*)d_in[9];
    const float* Dw     = (const float*)d_in[10];
    const float* outpw  = (const float*)d_in[11];
    const float* normf  = (const float*)d_in[12];
    float* out = (float*)d_out;

    float *x, *xr, *u, *xdbl, *delta, *part;
    cudaGetSymbolAddress((void**)&x,     g_x);
    cudaGetSymbolAddress((void**)&xr,    g_xr);
    cudaGetSymbolAddress((void**)&u,     g_u);
    cudaGetSymbolAddress((void**)&xdbl,  g_xdbl);
    cudaGetSymbolAddress((void**)&delta, g_delta);
    cudaGetSymbolAddress((void**)&part,  g_part);

    __half *emb_h, *emb_l, *inpw_h, *inpw_l, *outpw_h, *outpw_l;
    __half *xn_h, *xn_l, *u_h, *u_l, *y_h, *y_l;
    __half *xpw_h, *xpw_l, *dtw_h, *dtw_l, *xdp_h, *xdp_l;
    cudaGetSymbolAddress((void**)&emb_h,  g_emb_h);   cudaGetSymbolAddress((void**)&emb_l,  g_emb_l);
    cudaGetSymbolAddress((void**)&inpw_h, g_inpw_h);  cudaGetSymbolAddress((void**)&inpw_l, g_inpw_l);
    cudaGetSymbolAddress((void**)&outpw_h,g_outpw_h); cudaGetSymbolAddress((void**)&outpw_l,g_outpw_l);
    cudaGetSymbolAddress((void**)&xn_h,   g_xn_h);    cudaGetSymbolAddress((void**)&xn_l,   g_xn_l);
    cudaGetSymbolAddress((void**)&u_h,    g_u_h);     cudaGetSymbolAddress((void**)&u_l,    g_u_l);
    cudaGetSymbolAddress((void**)&y_h,    g_y_h);     cudaGetSymbolAddress((void**)&y_l,    g_y_l);
    cudaGetSymbolAddress((void**)&xpw_h,  g_xpw_h);   cudaGetSymbolAddress((void**)&xpw_l,  g_xpw_l);
    cudaGetSymbolAddress((void**)&dtw_h,  g_dtw_h);   cudaGetSymbolAddress((void**)&dtw_l,  g_dtw_l);
    cudaGetSymbolAddress((void**)&xdp_h,  g_xdp_h);   cudaGetSymbolAddress((void**)&xdp_l,  g_xdp_l);

    cudaFuncSetAttribute(mma_gemm<3>, cudaFuncAttributeMaxDynamicSharedMemorySize,
                         GSMEM_BYTES);
    cudaFuncSetAttribute(mma_gemm<2>, cudaFuncAttributeMaxDynamicSharedMemorySize,
                         GSMEM_BYTES);

    #define SPLIT4(src, n, h, l) \
        split4_kernel<<<((n)/4 + 255) / 256, 256>>>((const float4*)(src), (n)/4, \
            (__half2*)(h), (__half2*)(l))

    embed_kernel<<<M_ROWS, 256>>>(ids, emb, x);                               // 1
    SPLIT4(inpw, N_LAYER * 2 * D_INNER * D_MODEL, inpw_h, inpw_l);            // 2

    for (int lyr = 0; lyr < N_LAYER; lyr++) {
        rmsnorm_split_kernel<<<M_ROWS, 256>>>(x, normw + lyr * D_MODEL,
                                              xn_h, xn_l);                    // 3

        // in_proj (profiled control, launch #4)
        mma_gemm<3><<<dim3(2*D_INNER/128, M_ROWS/128, 1), 256, GSMEM_BYTES>>>(
            xn_h, xn_l,
            inpw_h + (long)lyr * 2*D_INNER*D_MODEL,
            inpw_l + (long)lyr * 2*D_INNER*D_MODEL,
            D_MODEL, D_MODEL, xr, 2*D_INNER, 2*D_INNER, nullptr, 0, 0);

        conv_silu_split_kernel<<<(M_ROWS*D_INNER/4 + 255)/256, 256>>>(
            xr, convw + lyr * D_INNER*D_CONV, convb + lyr * D_INNER,
            u, (__half2*)u_h, (__half2*)u_l);

        {
            int n4 = 128 * D_INNER / 4;
            split_pad_rows4<<<(n4 + 255)/256, 256>>>(
                xprojw + (long)lyr * XDBL_COLS * D_INNER, XDBL_COLS, D_INNER, 128,
                (__half2*)xpw_h, (__half2*)xpw_l);
        }
        mma_gemm<3><<<dim3(1, M_ROWS/128, 8), 256, GSMEM_BYTES>>>(
            u_h, u_l, xpw_h, xpw_l,
            D_INNER, D_INNER/8, part, 128, 128, nullptr, 0, (long)M_ROWS*128);
        reduce_xp_kernel<<<(M_ROWS*128 + 255)/256, 256>>>(part, xdbl, xdp_h, xdp_l);

        {
            int n4 = D_INNER * 64 / 4;
            split_pad_cols4<<<(n4 + 255)/256, 256>>>(
                dtpw + (long)lyr * D_INNER * DT_RANK, D_INNER, DT_RANK,
                DT_RANK, 64, (__half2*)dtw_h, (__half2*)dtw_l);
        }
        mma_gemm<3><<<dim3(D_INNER/128, M_ROWS/128, 1), 256, GSMEM_BYTES>>>(
            xdp_h, xdp_l, dtw_h, dtw_l,
            64, 64, delta, D_INNER, D_INNER, dtpb + lyr * D_INNER, 1, 0);

        scan_kernel<<<(BATCH*D_INNER)/16, 256>>>(
            delta, u, xdbl, xr, Alog + (long)lyr * D_INNER*D_STATE,
            Dw + lyr * D_INNER, y_h, y_l);

        if (lyr == 0)
            SPLIT4(outpw, N_LAYER * D_MODEL * D_INNER, outpw_h, outpw_l);

        mma_gemm<3><<<dim3(D_MODEL/128, M_ROWS/128, 4), 256, GSMEM_BYTES>>>(
            y_h, y_l,
            outpw_h + (long)lyr * D_MODEL*D_INNER,
            outpw_l + (long)lyr * D_MODEL*D_INNER,
            D_INNER, D_INNER/4, part, D_MODEL, D_MODEL, nullptr, 0,
            (long)M_ROWS*D_MODEL);
        reduce_out_kernel<<<(M_ROWS*D_MODEL/4 + 255)/256, 256>>>(part, x);
    }

    SPLIT4(emb, VOCAB * D_MODEL, emb_h, emb_l);
    rmsnorm_split_kernel<<<M_ROWS, 256>>>(x, normf, xn_h, xn_l);

    // logits: 2-term (A*Bh) — Bl never loaded
    mma_gemm<2><<<dim3(VOCAB/128, M_ROWS/128, 1), 256, GSMEM_BYTES>>>(
        xn_h, xn_l, emb_h, emb_l,
        D_MODEL, D_MODEL, out, VOCAB, VOCAB, nullptr, 0, 0);
}